// round 6
// baseline (speedup 1.0000x reference)
#include <cuda_runtime.h>
#include <cuda_bf16.h>
#include <math.h>
#include <stdint.h>

// ---------------- Problem constants ----------------
#define NE 256
#define KH 7168
#define MAX_T 16384
#define TOPK_GROUP 4
#define TOP_K 8
#define ROUTED_SCALE 2.5f
#define N_GROUP 8

// ---------------- GEMM config ----------------
#define BM 128
#define BN 128
#define BK 16
#define TMP 4              // row-PAIRS per thread (8 rows)
#define TN 8               // cols per thread

typedef unsigned long long u64;

__device__ float g_logits[MAX_T * NE];

__device__ __forceinline__ void fma2(u64& c, u64 a, u64 b) {
    asm volatile("fma.rn.f32x2 %0, %1, %2, %0;" : "+l"(c) : "l"(a), "l"(b));
}
__device__ __forceinline__ void unpack2(float& lo, float& hi, u64 v) {
    asm("mov.b64 {%0, %1}, %2;" : "=f"(lo), "=f"(hi) : "l"(v));
}

// ----------------------------------------------------------------------------
// GEMM: C[T,256] = A[T,7168] * B[7168,256]  -- exact fp32 via packed f32x2 FMA
// Numerics: per output element, identical fma.rn sequence (k ascending) to the
// scalar fp32 kernel that passed -> bitwise identical logits.
// ----------------------------------------------------------------------------
__global__ __launch_bounds__(256, 2)
void gate_gemm_f32x2(const float* __restrict__ A,
                     const float* __restrict__ B,
                     float* __restrict__ C)
{
    __shared__ float As[BK][BM];        // [k][m]
    __shared__ float Bs2[BK][BN * 2];   // [k][2n] duplicated pairs

    const int tid = threadIdx.x;
    const int tx = tid & 15;            // 16 -> TN=8 cols each: covers BN=128
    const int ty = tid >> 4;            // 16 -> 8 rows each: covers BM=128
    const int Mbase = blockIdx.y * BM;
    const int Nbase = blockIdx.x * BN;

    // A loader coords: 128 rows x 4 float4 chunks (BK=16); 2 rows per thread
    const int a_row  = tid >> 2;        // 0..63 (+64)
    const int a_col4 = tid & 3;
    // B loader coords: 16 k-rows x 32 float4 chunks; 2 chunks per thread
    const int b_row = tid >> 4;         // 0..15
    const int b_c   = tid & 15;         // chunk, +16 for second

    const float* Aptr = A + (size_t)(Mbase) * KH;
    const float* Bptr = B + Nbase;

    u64 acc[TMP][TN];
    #pragma unroll
    for (int p = 0; p < TMP; ++p)
        #pragma unroll
        for (int j = 0; j < TN; ++j) acc[p][j] = 0ull;

    for (int k0 = 0; k0 < KH; k0 += BK) {
        // --- load A tile transposed into As[k][m] ---
        #pragma unroll
        for (int r = 0; r < 2; ++r) {
            const int row = a_row + r * 64;
            float4 v = *(const float4*)(Aptr + (size_t)row * KH + k0 + a_col4 * 4);
            As[a_col4 * 4 + 0][row] = v.x;
            As[a_col4 * 4 + 1][row] = v.y;
            As[a_col4 * 4 + 2][row] = v.z;
            As[a_col4 * 4 + 3][row] = v.w;
        }
        // --- load B tile, store duplicated ---
        #pragma unroll
        for (int r = 0; r < 2; ++r) {
            const int c = b_c + r * 16;        // float4 chunk 0..31
            float4 v = *(const float4*)(Bptr + (size_t)(k0 + b_row) * NE + c * 4);
            float4 d0, d1;
            d0.x = v.x; d0.y = v.x; d0.z = v.y; d0.w = v.y;
            d1.x = v.z; d1.y = v.z; d1.z = v.w; d1.w = v.w;
            *(float4*)&Bs2[b_row][c * 8 + 0] = d0;
            *(float4*)&Bs2[b_row][c * 8 + 4] = d1;
        }
        __syncthreads();

        #pragma unroll
        for (int kk = 0; kk < BK; ++kk) {
            // a: 4 row-pairs (consecutive m), direct 64-bit loads
            const ulonglong2 a01 = *(const ulonglong2*)&As[kk][ty * 8];
            const ulonglong2 a23 = *(const ulonglong2*)&As[kk][ty * 8 + 4];
            u64 a[TMP] = {a01.x, a01.y, a23.x, a23.y};
            // b: 8 duplicated cols, direct 64-bit loads
            const ulonglong2 b01 = *(const ulonglong2*)&Bs2[kk][tx * 16 + 0];
            const ulonglong2 b23 = *(const ulonglong2*)&Bs2[kk][tx * 16 + 4];
            const ulonglong2 b45 = *(const ulonglong2*)&Bs2[kk][tx * 16 + 8];
            const ulonglong2 b67 = *(const ulonglong2*)&Bs2[kk][tx * 16 + 12];
            u64 b[TN] = {b01.x, b01.y, b23.x, b23.y, b45.x, b45.y, b67.x, b67.y};

            #pragma unroll
            for (int p = 0; p < TMP; ++p)
                #pragma unroll
                for (int j = 0; j < TN; ++j)
                    fma2(acc[p][j], a[p], b[j]);
        }
        __syncthreads();
    }

    // --- epilogue: unpack pairs, write two rows per pair ---
    #pragma unroll
    for (int p = 0; p < TMP; ++p) {
        const int r0 = Mbase + ty * 8 + 2 * p;
        float lo[TN], hi[TN];
        #pragma unroll
        for (int j = 0; j < TN; ++j) unpack2(lo[j], hi[j], acc[p][j]);
        float4 v;
        v.x = lo[0]; v.y = lo[1]; v.z = lo[2]; v.w = lo[3];
        *(float4*)&C[(size_t)r0 * NE + Nbase + tx * 8] = v;
        v.x = lo[4]; v.y = lo[5]; v.z = lo[6]; v.w = lo[7];
        *(float4*)&C[(size_t)r0 * NE + Nbase + tx * 8 + 4] = v;
        v.x = hi[0]; v.y = hi[1]; v.z = hi[2]; v.w = hi[3];
        *(float4*)&C[(size_t)(r0 + 1) * NE + Nbase + tx * 8] = v;
        v.x = hi[4]; v.y = hi[5]; v.z = hi[6]; v.w = hi[7];
        *(float4*)&C[(size_t)(r0 + 1) * NE + Nbase + tx * 8 + 4] = v;
    }
}

// ---------------- routing: one warp per token (validated in R2) ----------------
__global__ __launch_bounds__(256)
void route_kernel(const float* __restrict__ logits,
                  const float* __restrict__ bias,
                  float* __restrict__ out_idx,
                  float* __restrict__ out_w,
                  int T)
{
    const int gwarp = (blockIdx.x * blockDim.x + threadIdx.x) >> 5;
    const int lane = threadIdx.x & 31;
    if (gwarp >= T) return;

    const float* lp = logits + (size_t)gwarp * NE;

    float s[8];
    #pragma unroll
    for (int j = 0; j < 8; ++j) {
        const int e = lane * 8 + j;
        const float x = lp[e];
        s[j] = 1.0f / (1.0f + expf(-x)) + bias[e];
    }

    float m1 = -1e30f, m2 = -1e30f;
    #pragma unroll
    for (int j = 0; j < 8; ++j) {
        const float v = s[j];
        if (v > m1) { m2 = m1; m1 = v; }
        else if (v > m2) { m2 = v; }
    }
    #pragma unroll
    for (int off = 1; off < 4; off <<= 1) {
        const float o1 = __shfl_xor_sync(0xffffffffu, m1, off);
        const float o2 = __shfl_xor_sync(0xffffffffu, m2, off);
        const float n1 = fmaxf(m1, o1);
        const float n2 = fmaxf(fminf(m1, o1), fmaxf(m2, o2));
        m1 = n1; m2 = n2;
    }
    const float gscore = m1 + m2;

    float gs[N_GROUP];
    #pragma unroll
    for (int g = 0; g < N_GROUP; ++g)
        gs[g] = __shfl_sync(0xffffffffu, gscore, g * 4);

    unsigned gmask = 0;
    #pragma unroll
    for (int t = 0; t < TOPK_GROUP; ++t) {
        int best = 0; float bv = -1e30f;
        #pragma unroll
        for (int g = 0; g < N_GROUP; ++g)
            if (!((gmask >> g) & 1u) && gs[g] > bv) { bv = gs[g]; best = g; }
        gmask |= 1u << best;
    }

    const bool sel = (gmask >> (lane >> 2)) & 1u;
    float mv[8];
    #pragma unroll
    for (int j = 0; j < 8; ++j) mv[j] = sel ? s[j] : 0.0f;

    bool used[8];
    #pragma unroll
    for (int j = 0; j < 8; ++j) used[j] = false;

    float my_v = 0.0f; int my_i = 0; float vsum = 0.0f;
    #pragma unroll
    for (int t = 0; t < TOP_K; ++t) {
        float bv = -1e30f; int bi = NE;
        #pragma unroll
        for (int j = 0; j < 8; ++j) {
            if (!used[j]) {
                const float v = mv[j];
                const int e = lane * 8 + j;
                if (v > bv || (v == bv && e < bi)) { bv = v; bi = e; }
            }
        }
        #pragma unroll
        for (int off = 16; off > 0; off >>= 1) {
            const float ov = __shfl_xor_sync(0xffffffffu, bv, off);
            const int   oi = __shfl_xor_sync(0xffffffffu, bi, off);
            if (ov > bv || (ov == bv && oi < bi)) { bv = ov; bi = oi; }
        }
        if ((bi >> 3) == lane) used[bi & 7] = true;
        if (lane == t) { my_v = bv; my_i = bi; }
        vsum += bv;
    }

    const float scale = ROUTED_SCALE / (vsum + 1e-20f);
    if (lane < TOP_K) {
        out_idx[(size_t)gwarp * TOP_K + lane] = (float)my_i;
        out_w  [(size_t)gwarp * TOP_K + lane] = my_v * scale;
    }
}

// ---------------- launch ----------------
extern "C" void kernel_launch(void* const* d_in, const int* in_sizes, int n_in,
                              void* d_out, int out_size)
{
    const float* hs   = (const float*)d_in[0];
    const float* wk   = (const float*)d_in[1];
    const float* bias = (const float*)d_in[2];

    const int T = in_sizes[0] / KH;   // 16384

    float* logits;
    cudaGetSymbolAddress((void**)&logits, g_logits);

    dim3 grid(NE / BN, T / BM);
    gate_gemm_f32x2<<<grid, 256>>>(hs, wk, logits);

    float* out_f = (float*)d_out;
    float* out_idx = out_f;
    float* out_w   = out_f + (size_t)T * TOP_K;
    route_kernel<<<(T + 7) / 8, 256>>>(logits, bias, out_idx, out_w, T);
}

// round 7
// speedup vs baseline: 2.4679x; 2.4679x over previous
#include <cuda_runtime.h>
#include <cuda_bf16.h>
#include <math.h>
#include <stdint.h>

// ---------------- Problem constants ----------------
#define NE 256
#define KH 7168
#define MAX_T 16384
#define TOPK_GROUP 4
#define TOP_K 8
#define ROUTED_SCALE 2.5f
#define N_GROUP 8

// ---------------- GEMM config ----------------
#define BM 128
#define BN 128
#define BK 16
#define NCHUNKS (KH / BK)     // 448
#define TMP 4                 // row-pairs per thread (8 rows)
#define TN 8                  // cols per thread

typedef unsigned long long u64;

__device__ float g_logits[MAX_T * NE];

__device__ __forceinline__ void fma2(u64& c, u64 a, u64 b) {
    asm volatile("fma.rn.f32x2 %0, %1, %2, %0;" : "+l"(c) : "l"(a), "l"(b));
}
__device__ __forceinline__ void unpack2(float& lo, float& hi, u64 v) {
    asm("mov.b64 {%0, %1}, %2;" : "=f"(lo), "=f"(hi) : "l"(v));
}
__device__ __forceinline__ u64 pack_dup(float f) {
    u64 v;
    asm("mov.b64 %0, {%1, %1};" : "=l"(v) : "f"(f));
    return v;
}

// ----------------------------------------------------------------------------
// GEMM: C[T,256] = A[T,7168] * B[7168,256] -- exact fp32 via FFMA2 (f32x2)
// Per output element: single fma.rn chain, k ascending -> bitwise == scalar R2.
// B duplicated in smem as u64 Bd[kk][j][tx] -> conflict-free LDS.64.
// ----------------------------------------------------------------------------
__global__ __launch_bounds__(256, 1)
void gate_gemm_f32x2(const float* __restrict__ A,
                     const float* __restrict__ B,
                     float* __restrict__ C)
{
    __shared__ float As[BK][BM];          // [k][m]        8 KB
    __shared__ u64  Bd[BK][TN][16];       // [k][j][tx]   16 KB (dup pairs)

    const int tid = threadIdx.x;
    const int tx = tid & 15;              // 16 -> 8 cols each (BN=128)
    const int ty = tid >> 4;              // 16 -> 8 rows each (BM=128)
    const int Mbase = blockIdx.y * BM;
    const int Nbase = blockIdx.x * BN;

    // A loader: 128 rows x 4 float4-chunks; 2 rows per thread
    const int a_row  = tid >> 2;          // 0..63 (+64)
    const int a_col4 = tid & 3;
    // B loader: 16 k-rows x 32 float4-chunks; 2 chunks per thread
    const int b_row = tid >> 4;           // 0..15
    const int b_c   = tid & 15;           // chunk, +16 for second

    const float* Aptr = A + (size_t)Mbase * KH;
    const float* Bptr = B + Nbase;

    // prefetch registers
    float4 pa[2], pb[2];

    auto load_regs = [&](int c) {
        const int k0 = c * BK;
        #pragma unroll
        for (int r = 0; r < 2; ++r)
            pa[r] = *(const float4*)(Aptr + (size_t)(a_row + r * 64) * KH + k0 + a_col4 * 4);
        #pragma unroll
        for (int r = 0; r < 2; ++r)
            pb[r] = *(const float4*)(Bptr + (size_t)(k0 + b_row) * NE + (b_c + r * 16) * 4);
    };

    auto sts = [&]() {
        // A transpose-store
        #pragma unroll
        for (int r = 0; r < 2; ++r) {
            const int row = a_row + r * 64;
            As[a_col4 * 4 + 0][row] = pa[r].x;
            As[a_col4 * 4 + 1][row] = pa[r].y;
            As[a_col4 * 4 + 2][row] = pa[r].z;
            As[a_col4 * 4 + 3][row] = pa[r].w;
        }
        // B dup-store: float at col n -> Bd[b_row][n&7][n>>3]
        #pragma unroll
        for (int r = 0; r < 2; ++r) {
            const int n0 = (b_c + r * 16) * 4;
            const int j0 = n0 & 7;
            const int t0 = n0 >> 3;
            Bd[b_row][j0 + 0][t0] = pack_dup(pb[r].x);
            Bd[b_row][j0 + 1][t0] = pack_dup(pb[r].y);
            Bd[b_row][j0 + 2][t0] = pack_dup(pb[r].z);
            Bd[b_row][j0 + 3][t0] = pack_dup(pb[r].w);
        }
    };

    u64 acc[TMP][TN];
    #pragma unroll
    for (int p = 0; p < TMP; ++p)
        #pragma unroll
        for (int j = 0; j < TN; ++j) acc[p][j] = 0ull;

    load_regs(0);

    for (int c = 0; c < NCHUNKS; ++c) {
        sts();
        __syncthreads();
        if (c + 1 < NCHUNKS) load_regs(c + 1);   // LDG overlaps compute below

        #pragma unroll
        for (int kk = 0; kk < BK; ++kk) {
            const ulonglong2 a01 = *(const ulonglong2*)&As[kk][ty * 8];
            const ulonglong2 a23 = *(const ulonglong2*)&As[kk][ty * 8 + 4];
            u64 a[TMP] = {a01.x, a01.y, a23.x, a23.y};
            u64 b[TN];
            #pragma unroll
            for (int j = 0; j < TN; ++j) b[j] = Bd[kk][j][tx];

            #pragma unroll
            for (int p = 0; p < TMP; ++p)
                #pragma unroll
                for (int j = 0; j < TN; ++j)
                    fma2(acc[p][j], a[p], b[j]);
        }
        __syncthreads();
    }

    // epilogue: unpack pairs, write two rows per pair
    #pragma unroll
    for (int p = 0; p < TMP; ++p) {
        const int r0 = Mbase + ty * 8 + 2 * p;
        float lo[TN], hi[TN];
        #pragma unroll
        for (int j = 0; j < TN; ++j) unpack2(lo[j], hi[j], acc[p][j]);
        float4 v;
        v.x = lo[0]; v.y = lo[1]; v.z = lo[2]; v.w = lo[3];
        *(float4*)&C[(size_t)r0 * NE + Nbase + tx * 8] = v;
        v.x = lo[4]; v.y = lo[5]; v.z = lo[6]; v.w = lo[7];
        *(float4*)&C[(size_t)r0 * NE + Nbase + tx * 8 + 4] = v;
        v.x = hi[0]; v.y = hi[1]; v.z = hi[2]; v.w = hi[3];
        *(float4*)&C[(size_t)(r0 + 1) * NE + Nbase + tx * 8] = v;
        v.x = hi[4]; v.y = hi[5]; v.z = hi[6]; v.w = hi[7];
        *(float4*)&C[(size_t)(r0 + 1) * NE + Nbase + tx * 8 + 4] = v;
    }
}

// ---------------- routing: one warp per token (validated) ----------------
__global__ __launch_bounds__(256)
void route_kernel(const float* __restrict__ logits,
                  const float* __restrict__ bias,
                  float* __restrict__ out_idx,
                  float* __restrict__ out_w,
                  int T)
{
    const int gwarp = (blockIdx.x * blockDim.x + threadIdx.x) >> 5;
    const int lane = threadIdx.x & 31;
    if (gwarp >= T) return;

    const float* lp = logits + (size_t)gwarp * NE;

    float s[8];
    #pragma unroll
    for (int j = 0; j < 8; ++j) {
        const int e = lane * 8 + j;
        const float x = lp[e];
        s[j] = 1.0f / (1.0f + expf(-x)) + bias[e];
    }

    float m1 = -1e30f, m2 = -1e30f;
    #pragma unroll
    for (int j = 0; j < 8; ++j) {
        const float v = s[j];
        if (v > m1) { m2 = m1; m1 = v; }
        else if (v > m2) { m2 = v; }
    }
    #pragma unroll
    for (int off = 1; off < 4; off <<= 1) {
        const float o1 = __shfl_xor_sync(0xffffffffu, m1, off);
        const float o2 = __shfl_xor_sync(0xffffffffu, m2, off);
        const float n1 = fmaxf(m1, o1);
        const float n2 = fmaxf(fminf(m1, o1), fmaxf(m2, o2));
        m1 = n1; m2 = n2;
    }
    const float gscore = m1 + m2;

    float gs[N_GROUP];
    #pragma unroll
    for (int g = 0; g < N_GROUP; ++g)
        gs[g] = __shfl_sync(0xffffffffu, gscore, g * 4);

    unsigned gmask = 0;
    #pragma unroll
    for (int t = 0; t < TOPK_GROUP; ++t) {
        int best = 0; float bv = -1e30f;
        #pragma unroll
        for (int g = 0; g < N_GROUP; ++g)
            if (!((gmask >> g) & 1u) && gs[g] > bv) { bv = gs[g]; best = g; }
        gmask |= 1u << best;
    }

    const bool sel = (gmask >> (lane >> 2)) & 1u;
    float mv[8];
    #pragma unroll
    for (int j = 0; j < 8; ++j) mv[j] = sel ? s[j] : 0.0f;

    bool used[8];
    #pragma unroll
    for (int j = 0; j < 8; ++j) used[j] = false;

    float my_v = 0.0f; int my_i = 0; float vsum = 0.0f;
    #pragma unroll
    for (int t = 0; t < TOP_K; ++t) {
        float bv = -1e30f; int bi = NE;
        #pragma unroll
        for (int j = 0; j < 8; ++j) {
            if (!used[j]) {
                const float v = mv[j];
                const int e = lane * 8 + j;
                if (v > bv || (v == bv && e < bi)) { bv = v; bi = e; }
            }
        }
        #pragma unroll
        for (int off = 16; off > 0; off >>= 1) {
            const float ov = __shfl_xor_sync(0xffffffffu, bv, off);
            const int   oi = __shfl_xor_sync(0xffffffffu, bi, off);
            if (ov > bv || (ov == bv && oi < bi)) { bv = ov; bi = oi; }
        }
        if ((bi >> 3) == lane) used[bi & 7] = true;
        if (lane == t) { my_v = bv; my_i = bi; }
        vsum += bv;
    }

    const float scale = ROUTED_SCALE / (vsum + 1e-20f);
    if (lane < TOP_K) {
        out_idx[(size_t)gwarp * TOP_K + lane] = (float)my_i;
        out_w  [(size_t)gwarp * TOP_K + lane] = my_v * scale;
    }
}

// ---------------- launch ----------------
extern "C" void kernel_launch(void* const* d_in, const int* in_sizes, int n_in,
                              void* d_out, int out_size)
{
    const float* hs   = (const float*)d_in[0];
    const float* wk   = (const float*)d_in[1];
    const float* bias = (const float*)d_in[2];

    const int T = in_sizes[0] / KH;   // 16384

    float* logits;
    cudaGetSymbolAddress((void**)&logits, g_logits);

    dim3 grid(NE / BN, T / BM);
    gate_gemm_f32x2<<<grid, 256>>>(hs, wk, logits);

    float* out_f = (float*)d_out;
    float* out_idx = out_f;
    float* out_w   = out_f + (size_t)T * TOP_K;
    route_kernel<<<(T + 7) / 8, 256>>>(logits, bias, out_idx, out_w, T);
}

// round 8
// speedup vs baseline: 2.5882x; 1.0487x over previous
#include <cuda_runtime.h>
#include <cuda_bf16.h>
#include <math.h>
#include <stdint.h>

// ---------------- Problem constants ----------------
#define NE 256
#define KH 7168
#define MAX_T 16384
#define TOPK_GROUP 4
#define TOP_K 8
#define ROUTED_SCALE 2.5f
#define N_GROUP 8

// margin thresholds (score units). error std ~1e-7 -> huge safety factor.
#define TAU_E 3e-5f
#define TAU_G 1e-4f

// ---------------- approx GEMM config (validated machinery from R4) ----------------
#define BM 128
#define BN 128
#define BKC 32
#define NCH (KH / BKC)         // 224
#define ASTR 40
#define BSTR 136
#define AH_OFF 0
#define AL_OFF (BM * ASTR * 2)
#define BH_OFF (2 * BM * ASTR * 2)
#define BL_OFF (BH_OFF + BKC * BSTR * 2)
#define STAGE  (BL_OFF + BKC * BSTR * 2)
#define SMEM_TOTAL (2 * STAGE)

// fallback config
#define FB_TOK 4
#define FB_SMEM (KH * FB_TOK * 4)     // 114688 bytes

// ---------------- device scratch ----------------
__device__ float g_logits[MAX_T * NE];
__device__ __nv_bfloat16 g_bhi[KH * NE];
__device__ __nv_bfloat16 g_blo[KH * NE];
__device__ int g_list[MAX_T];
__device__ int g_count;

// ---------------- helpers ----------------
__device__ __forceinline__ uint32_t smem_u32(const void* p) {
    uint32_t a;
    asm("{ .reg .u64 t; cvta.to.shared.u64 t, %1; cvt.u32.u64 %0, t; }" : "=r"(a) : "l"(p));
    return a;
}
__device__ __forceinline__ void ldsm_x4(uint32_t* r, uint32_t addr) {
    asm volatile("ldmatrix.sync.aligned.m8n8.x4.shared.b16 {%0,%1,%2,%3}, [%4];"
                 : "=r"(r[0]), "=r"(r[1]), "=r"(r[2]), "=r"(r[3]) : "r"(addr));
}
__device__ __forceinline__ void ldsm_x2t(uint32_t* r, uint32_t addr) {
    asm volatile("ldmatrix.sync.aligned.m8n8.x2.trans.shared.b16 {%0,%1}, [%2];"
                 : "=r"(r[0]), "=r"(r[1]) : "r"(addr));
}
__device__ __forceinline__ void mma_bf16(float* c, const uint32_t* a, const uint32_t* b) {
    asm volatile("mma.sync.aligned.m16n8k16.row.col.f32.bf16.bf16.f32 "
                 "{%0,%1,%2,%3}, {%4,%5,%6,%7}, {%8,%9}, {%0,%1,%2,%3};"
                 : "+f"(c[0]), "+f"(c[1]), "+f"(c[2]), "+f"(c[3])
                 : "r"(a[0]), "r"(a[1]), "r"(a[2]), "r"(a[3]), "r"(b[0]), "r"(b[1]));
}

// ---------------- init ----------------
__global__ void init_kernel() { g_count = 0; }

// ---------------- B split: [K,N] fp32 -> [K,N] bf16 hi/lo ----------------
__global__ __launch_bounds__(256)
void split_b_kernel(const float* __restrict__ B,
                    __nv_bfloat16* __restrict__ bhi,
                    __nv_bfloat16* __restrict__ blo)
{
    const int idx = blockIdx.x * 256 + threadIdx.x;
    if (idx >= KH * NE) return;
    const float v = B[idx];
    const __nv_bfloat16 h = __float2bfloat16(v);
    bhi[idx] = h;
    blo[idx] = __float2bfloat16(v - __bfloat162float(h));
}

// ---------------- approx GEMM: 3-term split-bf16 mma.sync (from R4, verified) ---
__global__ __launch_bounds__(256)
void gate_gemm_mma(const float* __restrict__ A,
                   const __nv_bfloat16* __restrict__ Bhi,
                   const __nv_bfloat16* __restrict__ Blo,
                   float* __restrict__ C)
{
    extern __shared__ char smem[];
    const uint32_t sb = smem_u32(smem);
    const int tid = threadIdx.x;
    const int wid = tid >> 5, lane = tid & 31;
    const int Mbase = blockIdx.y * BM, Nbase = blockIdx.x * BN;
    const int mw = (wid & 3) * 32;
    const int nw = (wid >> 2) * 64;

    const int l7 = lane & 7, l8 = (lane >> 3) & 1, l16 = lane >> 4;
    uint32_t a_rel[2];
    #pragma unroll
    for (int tm = 0; tm < 2; ++tm)
        a_rel[tm] = (uint32_t)(((mw + 16 * tm + l7 + 8 * l8) * ASTR + 8 * l16) * 2);
    uint32_t b_rel[8];
    #pragma unroll
    for (int tn = 0; tn < 8; ++tn)
        b_rel[tn] = (uint32_t)(((l7 + 8 * l8) * BSTR + nw + 8 * tn) * 2);

    const int ar = tid >> 1, ahf = tid & 1;
    const float* Aptr = A + (size_t)(Mbase + ar) * KH + ahf * 16;
    const uint32_t a_sts_rel = (uint32_t)((ar * ASTR + ahf * 16) * 2);

    const int bkr = tid >> 4, bnc = tid & 15;
    const __nv_bfloat16* BhP = Bhi + (size_t)bkr * NE + Nbase + bnc * 8;
    const __nv_bfloat16* BlP = Blo + (size_t)bkr * NE + Nbase + bnc * 8;
    const uint32_t b_sts_rel = (uint32_t)((bkr * BSTR + bnc * 8) * 2);

    float4 arg[4];
    uint4 bh0, bh1, bl0, bl1;

    auto load_regs = [&](int c) {
        const float* ap = Aptr + c * BKC;
        #pragma unroll
        for (int i = 0; i < 4; ++i) arg[i] = *(const float4*)(ap + 4 * i);
        const size_t bo = (size_t)c * BKC * NE;
        bh0 = *(const uint4*)(BhP + bo);
        bh1 = *(const uint4*)(BhP + bo + (size_t)16 * NE);
        bl0 = *(const uint4*)(BlP + bo);
        bl1 = *(const uint4*)(BlP + bo + (size_t)16 * NE);
    };

    auto sts = [&](int s) {
        char* base = smem + s * STAGE;
        #pragma unroll
        for (int i = 0; i < 4; ++i) {
            const float4 v = arg[i];
            __nv_bfloat162 h01 = __floats2bfloat162_rn(v.x, v.y);
            __nv_bfloat162 h23 = __floats2bfloat162_rn(v.z, v.w);
            __nv_bfloat162 l01 = __floats2bfloat162_rn(v.x - __bfloat162float(h01.x),
                                                       v.y - __bfloat162float(h01.y));
            __nv_bfloat162 l23 = __floats2bfloat162_rn(v.z - __bfloat162float(h23.x),
                                                       v.w - __bfloat162float(h23.y));
            uint2 hv, lv;
            hv.x = *(uint32_t*)&h01; hv.y = *(uint32_t*)&h23;
            lv.x = *(uint32_t*)&l01; lv.y = *(uint32_t*)&l23;
            *(uint2*)(base + AH_OFF + a_sts_rel + 8 * i) = hv;
            *(uint2*)(base + AL_OFF + a_sts_rel + 8 * i) = lv;
        }
        *(uint4*)(base + BH_OFF + b_sts_rel) = bh0;
        *(uint4*)(base + BH_OFF + b_sts_rel + 16 * BSTR * 2) = bh1;
        *(uint4*)(base + BL_OFF + b_sts_rel) = bl0;
        *(uint4*)(base + BL_OFF + b_sts_rel + 16 * BSTR * 2) = bl1;
    };

    float acc[2][8][4];
    #pragma unroll
    for (int i = 0; i < 2; ++i)
        #pragma unroll
        for (int j = 0; j < 8; ++j)
            #pragma unroll
            for (int k = 0; k < 4; ++k) acc[i][j][k] = 0.0f;

    load_regs(0);
    sts(0);
    __syncthreads();
    load_regs(1);

    for (int c = 0; c < NCH; ++c) {
        const uint32_t stg = sb + (uint32_t)((c & 1) * STAGE);
        #pragma unroll
        for (int ks = 0; ks < 2; ++ks) {
            const uint32_t ko = ks * 16;
            uint32_t ah[2][4], al[2][4], bh[8][2], bl[8][2];
            #pragma unroll
            for (int tm = 0; tm < 2; ++tm) {
                ldsm_x4(ah[tm], stg + AH_OFF + a_rel[tm] + ko * 2);
                ldsm_x4(al[tm], stg + AL_OFF + a_rel[tm] + ko * 2);
            }
            #pragma unroll
            for (int tn = 0; tn < 8; ++tn) {
                ldsm_x2t(bh[tn], stg + BH_OFF + b_rel[tn] + ko * (BSTR * 2));
                ldsm_x2t(bl[tn], stg + BL_OFF + b_rel[tn] + ko * (BSTR * 2));
            }
            #pragma unroll
            for (int tm = 0; tm < 2; ++tm)
                #pragma unroll
                for (int tn = 0; tn < 8; ++tn) {
                    mma_bf16(acc[tm][tn], ah[tm], bh[tn]);
                    mma_bf16(acc[tm][tn], ah[tm], bl[tn]);
                    mma_bf16(acc[tm][tn], al[tm], bh[tn]);
                }
        }
        if (c + 1 < NCH) {
            sts((c + 1) & 1);
            __syncthreads();
            if (c + 2 < NCH) load_regs(c + 2);
        }
    }

    #pragma unroll
    for (int tm = 0; tm < 2; ++tm) {
        const int r0 = Mbase + mw + 16 * tm + (lane >> 2);
        #pragma unroll
        for (int tn = 0; tn < 8; ++tn) {
            const int cc = Nbase + nw + 8 * tn + 2 * (lane & 3);
            float2 v0, v1;
            v0.x = acc[tm][tn][0]; v0.y = acc[tm][tn][1];
            v1.x = acc[tm][tn][2]; v1.y = acc[tm][tn][3];
            *(float2*)&C[(size_t)r0 * NE + cc] = v0;
            *(float2*)&C[(size_t)(r0 + 8) * NE + cc] = v1;
        }
    }
}

// ---------------- pass 1: route + margin detection ----------------
__global__ __launch_bounds__(256)
void route_pass1(const float* __restrict__ logits,
                 const float* __restrict__ bias,
                 float* __restrict__ out_idx,
                 float* __restrict__ out_w,
                 int* __restrict__ list,
                 int T)
{
    const int gwarp = (blockIdx.x * blockDim.x + threadIdx.x) >> 5;
    const int lane = threadIdx.x & 31;
    if (gwarp >= T) return;

    const float* lp = logits + (size_t)gwarp * NE;

    float s[8];
    #pragma unroll
    for (int j = 0; j < 8; ++j) {
        const int e = lane * 8 + j;
        s[j] = 1.0f / (1.0f + expf(-lp[e])) + bias[e];
    }

    // per-lane top-2 then group (4 lanes) top-2
    float m1 = -1e30f, m2 = -1e30f;
    #pragma unroll
    for (int j = 0; j < 8; ++j) {
        const float v = s[j];
        if (v > m1) { m2 = m1; m1 = v; }
        else if (v > m2) { m2 = v; }
    }
    #pragma unroll
    for (int off = 1; off < 4; off <<= 1) {
        const float o1 = __shfl_xor_sync(0xffffffffu, m1, off);
        const float o2 = __shfl_xor_sync(0xffffffffu, m2, off);
        const float n1 = fmaxf(m1, o1);
        const float n2 = fmaxf(fminf(m1, o1), fmaxf(m2, o2));
        m1 = n1; m2 = n2;
    }
    const float gscore = m1 + m2;

    float gs[N_GROUP];
    #pragma unroll
    for (int g = 0; g < N_GROUP; ++g)
        gs[g] = __shfl_sync(0xffffffffu, gscore, g * 4);

    // top-5 group picks: mask from first 4, margin = 4th - 5th
    unsigned gmask = 0;
    float g4 = 0.0f, g5 = 0.0f;
    #pragma unroll
    for (int t = 0; t < 5; ++t) {
        int best = 0; float bv = -1e30f;
        #pragma unroll
        for (int g = 0; g < N_GROUP; ++g)
            if (!((gmask >> g) & 1u) && gs[g] > bv) { bv = gs[g]; best = g; }
        if (t < 4) { gmask |= 1u << best; if (t == 3) g4 = bv; }
        else g5 = bv;
    }
    bool flag = (g4 - g5) < TAU_G;

    const bool sel = (gmask >> (lane >> 2)) & 1u;
    float mv[8];
    #pragma unroll
    for (int j = 0; j < 8; ++j) mv[j] = sel ? s[j] : 0.0f;

    bool used[8];
    #pragma unroll
    for (int j = 0; j < 8; ++j) used[j] = false;

    float my_v = 0.0f; int my_i = 0; float vsum = 0.0f;
    float prev = 0.0f;
    #pragma unroll
    for (int t = 0; t < TOP_K + 1; ++t) {     // 9 picks: 8 outputs + margin probe
        float bv = -1e30f; int bi = NE;
        #pragma unroll
        for (int j = 0; j < 8; ++j) {
            if (!used[j]) {
                const float v = mv[j];
                const int e = lane * 8 + j;
                if (v > bv || (v == bv && e < bi)) { bv = v; bi = e; }
            }
        }
        #pragma unroll
        for (int off = 16; off > 0; off >>= 1) {
            const float ov = __shfl_xor_sync(0xffffffffu, bv, off);
            const int   oi = __shfl_xor_sync(0xffffffffu, bi, off);
            if (ov > bv || (ov == bv && oi < bi)) { bv = ov; bi = oi; }
        }
        if (t > 0) flag = flag || ((prev - bv) < TAU_E);
        prev = bv;
        if (t < TOP_K) {
            if ((bi >> 3) == lane) used[bi & 7] = true;
            if (lane == t) { my_v = bv; my_i = bi; }
            vsum += bv;
        }
    }

    const float scale = ROUTED_SCALE / (vsum + 1e-20f);
    if (lane < TOP_K) {
        out_idx[(size_t)gwarp * TOP_K + lane] = (float)my_i;
        out_w  [(size_t)gwarp * TOP_K + lane] = my_v * scale;
    }
    if (flag && lane == 0) {
        const int p = atomicAdd(&g_count, 1);
        if (p < MAX_T) list[p] = gwarp;
    }
}

// ---------------- fallback: exact fp32 logits for marked tokens ----------------
__global__ __launch_bounds__(256)
void fb_gemm(const float* __restrict__ A,
             const float* __restrict__ B,
             float* __restrict__ logits,
             const int* __restrict__ list)
{
    const int count = g_count;
    const int base = blockIdx.x * FB_TOK;
    if (base >= count) return;

    extern __shared__ float As[];     // As[k*FB_TOK + t]
    const int tid = threadIdx.x;

    int tok[FB_TOK];
    #pragma unroll
    for (int t = 0; t < FB_TOK; ++t)
        tok[t] = (base + t < count) ? list[base + t] : list[base];

    // cooperative load: thread handles token t = tid/64, consecutive k
    {
        const int t = tid >> 6;            // 0..3
        const int sub = tid & 63;          // 64 threads per token
        const float* arow = A + (size_t)tok[t] * KH;
        for (int k = sub; k < KH; k += 64)
            As[k * FB_TOK + t] = arow[k];
    }
    __syncthreads();

    const int e = tid;                     // expert
    const float* bcol = B + e;
    float acc[FB_TOK] = {0.f, 0.f, 0.f, 0.f};

    #pragma unroll 8
    for (int k = 0; k < KH; ++k) {
        const float b = bcol[(size_t)k * NE];
        const float4 a = *(const float4*)&As[k * FB_TOK];
        acc[0] = fmaf(a.x, b, acc[0]);
        acc[1] = fmaf(a.y, b, acc[1]);
        acc[2] = fmaf(a.z, b, acc[2]);
        acc[3] = fmaf(a.w, b, acc[3]);
    }

    #pragma unroll
    for (int t = 0; t < FB_TOK; ++t)
        logits[(size_t)tok[t] * NE + e] = acc[t];
}

// ---------------- pass 2: exact re-route of marked tokens ----------------
__global__ __launch_bounds__(256)
void route_pass2(const float* __restrict__ logits,
                 const float* __restrict__ bias,
                 float* __restrict__ out_idx,
                 float* __restrict__ out_w,
                 const int* __restrict__ list)
{
    const int w = (blockIdx.x * blockDim.x + threadIdx.x) >> 5;
    const int lane = threadIdx.x & 31;
    if (w >= g_count) return;
    const int token = list[w];

    const float* lp = logits + (size_t)token * NE;

    float s[8];
    #pragma unroll
    for (int j = 0; j < 8; ++j) {
        const int e = lane * 8 + j;
        s[j] = 1.0f / (1.0f + expf(-lp[e])) + bias[e];
    }

    float m1 = -1e30f, m2 = -1e30f;
    #pragma unroll
    for (int j = 0; j < 8; ++j) {
        const float v = s[j];
        if (v > m1) { m2 = m1; m1 = v; }
        else if (v > m2) { m2 = v; }
    }
    #pragma unroll
    for (int off = 1; off < 4; off <<= 1) {
        const float o1 = __shfl_xor_sync(0xffffffffu, m1, off);
        const float o2 = __shfl_xor_sync(0xffffffffu, m2, off);
        const float n1 = fmaxf(m1, o1);
        const float n2 = fmaxf(fminf(m1, o1), fmaxf(m2, o2));
        m1 = n1; m2 = n2;
    }
    const float gscore = m1 + m2;

    float gs[N_GROUP];
    #pragma unroll
    for (int g = 0; g < N_GROUP; ++g)
        gs[g] = __shfl_sync(0xffffffffu, gscore, g * 4);

    unsigned gmask = 0;
    #pragma unroll
    for (int t = 0; t < TOPK_GROUP; ++t) {
        int best = 0; float bv = -1e30f;
        #pragma unroll
        for (int g = 0; g < N_GROUP; ++g)
            if (!((gmask >> g) & 1u) && gs[g] > bv) { bv = gs[g]; best = g; }
        gmask |= 1u << best;
    }

    const bool sel = (gmask >> (lane >> 2)) & 1u;
    float mv[8];
    #pragma unroll
    for (int j = 0; j < 8; ++j) mv[j] = sel ? s[j] : 0.0f;

    bool used[8];
    #pragma unroll
    for (int j = 0; j < 8; ++j) used[j] = false;

    float my_v = 0.0f; int my_i = 0; float vsum = 0.0f;
    #pragma unroll
    for (int t = 0; t < TOP_K; ++t) {
        float bv = -1e30f; int bi = NE;
        #pragma unroll
        for (int j = 0; j < 8; ++j) {
            if (!used[j]) {
                const float v = mv[j];
                const int e = lane * 8 + j;
                if (v > bv || (v == bv && e < bi)) { bv = v; bi = e; }
            }
        }
        #pragma unroll
        for (int off = 16; off > 0; off >>= 1) {
            const float ov = __shfl_xor_sync(0xffffffffu, bv, off);
            const int   oi = __shfl_xor_sync(0xffffffffu, bi, off);
            if (ov > bv || (ov == bv && oi < bi)) { bv = ov; bi = oi; }
        }
        if ((bi >> 3) == lane) used[bi & 7] = true;
        if (lane == t) { my_v = bv; my_i = bi; }
        vsum += bv;
    }

    const float scale = ROUTED_SCALE / (vsum + 1e-20f);
    if (lane < TOP_K) {
        out_idx[(size_t)token * TOP_K + lane] = (float)my_i;
        out_w  [(size_t)token * TOP_K + lane] = my_v * scale;
    }
}

// ---------------- launch ----------------
extern "C" void kernel_launch(void* const* d_in, const int* in_sizes, int n_in,
                              void* d_out, int out_size)
{
    const float* hs   = (const float*)d_in[0];
    const float* wk   = (const float*)d_in[1];
    const float* bias = (const float*)d_in[2];

    const int T = in_sizes[0] / KH;   // 16384

    float* logits;      cudaGetSymbolAddress((void**)&logits, g_logits);
    __nv_bfloat16* bhi; cudaGetSymbolAddress((void**)&bhi, g_bhi);
    __nv_bfloat16* blo; cudaGetSymbolAddress((void**)&blo, g_blo);
    int* list;          cudaGetSymbolAddress((void**)&list, g_list);

    float* out_f = (float*)d_out;
    float* out_idx = out_f;
    float* out_w   = out_f + (size_t)T * TOP_K;

    init_kernel<<<1, 1>>>();
    split_b_kernel<<<(KH * NE + 255) / 256, 256>>>(wk, bhi, blo);

    cudaFuncSetAttribute(gate_gemm_mma, cudaFuncAttributeMaxDynamicSharedMemorySize, SMEM_TOTAL);
    dim3 grid(NE / BN, T / BM);
    gate_gemm_mma<<<grid, 256, SMEM_TOTAL>>>(hs, bhi, blo, logits);

    route_pass1<<<(T + 7) / 8, 256>>>(logits, bias, out_idx, out_w, list, T);

    cudaFuncSetAttribute(fb_gemm, cudaFuncAttributeMaxDynamicSharedMemorySize, FB_SMEM);
    fb_gemm<<<(MAX_T + FB_TOK - 1) / FB_TOK, 256, FB_SMEM>>>(hs, wk, logits, list);

    route_pass2<<<(MAX_T + 7) / 8, 256>>>(logits, bias, out_idx, out_w, list);
}

// round 9
// speedup vs baseline: 4.3077x; 1.6644x over previous
#include <cuda_runtime.h>
#include <cuda_bf16.h>
#include <math.h>
#include <stdint.h>

// ---------------- Problem constants ----------------
#define NE 256
#define KH 7168
#define MAX_T 16384
#define TOPK_GROUP 4
#define TOP_K 8
#define ROUTED_SCALE 2.5f
#define N_GROUP 8

#define TAU_E 3e-5f
#define TAU_G 1e-4f

// ---------------- GEMM config ----------------
#define BM 128
#define BN 128
#define NCH_ST (KH / 32)        // 224 stages of K=32
// smem stage layout (bytes)
#define AHI_OFF 0
#define ALO_OFF 10240
#define BHI_OFF 20480
#define BLO_OFF 29184
#define STAGE   37888
#define NSTAGE  4
#define SMEM_TOTAL (NSTAGE * STAGE)   // 151552

// ---------------- device scratch ----------------
__device__ float g_logits[MAX_T * NE];
__device__ __nv_bfloat16 g_ahi[(size_t)MAX_T * KH];
__device__ __nv_bfloat16 g_alo[(size_t)MAX_T * KH];
__device__ __nv_bfloat16 g_bhi[KH * NE];
__device__ __nv_bfloat16 g_blo[KH * NE];
__device__ int g_list[MAX_T];
__device__ int g_count;

// ---------------- helpers ----------------
__device__ __forceinline__ uint32_t smem_u32(const void* p) {
    uint32_t a;
    asm("{ .reg .u64 t; cvta.to.shared.u64 t, %1; cvt.u32.u64 %0, t; }" : "=r"(a) : "l"(p));
    return a;
}
__device__ __forceinline__ void cpa16(uint32_t dst, const void* src) {
    asm volatile("cp.async.cg.shared.global [%0], [%1], 16;" :: "r"(dst), "l"(src));
}
__device__ __forceinline__ void ldsm_x4(uint32_t* r, uint32_t addr) {
    asm volatile("ldmatrix.sync.aligned.m8n8.x4.shared.b16 {%0,%1,%2,%3}, [%4];"
                 : "=r"(r[0]), "=r"(r[1]), "=r"(r[2]), "=r"(r[3]) : "r"(addr));
}
__device__ __forceinline__ void ldsm_x2t(uint32_t* r, uint32_t addr) {
    asm volatile("ldmatrix.sync.aligned.m8n8.x2.trans.shared.b16 {%0,%1}, [%2];"
                 : "=r"(r[0]), "=r"(r[1]) : "r"(addr));
}
__device__ __forceinline__ void mma_bf16(float* c, const uint32_t* a, const uint32_t* b) {
    asm volatile("mma.sync.aligned.m16n8k16.row.col.f32.bf16.bf16.f32 "
                 "{%0,%1,%2,%3}, {%4,%5,%6,%7}, {%8,%9}, {%0,%1,%2,%3};"
                 : "+f"(c[0]), "+f"(c[1]), "+f"(c[2]), "+f"(c[3])
                 : "r"(a[0]), "r"(a[1]), "r"(a[2]), "r"(a[3]), "r"(b[0]), "r"(b[1]));
}

__global__ void init_kernel() { g_count = 0; }

// ---------------- split A: [T,KH] fp32 -> bf16 hi/lo ----------------
__global__ __launch_bounds__(256)
void split_a_kernel(const float* __restrict__ A,
                    __nv_bfloat16* __restrict__ ahi,
                    __nv_bfloat16* __restrict__ alo)
{
    const size_t i = ((size_t)blockIdx.x * 256 + threadIdx.x) * 4;
    const float4 v = *(const float4*)(A + i);
    __nv_bfloat162 h01 = __floats2bfloat162_rn(v.x, v.y);
    __nv_bfloat162 h23 = __floats2bfloat162_rn(v.z, v.w);
    __nv_bfloat162 l01 = __floats2bfloat162_rn(v.x - __bfloat162float(h01.x),
                                               v.y - __bfloat162float(h01.y));
    __nv_bfloat162 l23 = __floats2bfloat162_rn(v.z - __bfloat162float(h23.x),
                                               v.w - __bfloat162float(h23.y));
    uint2 hv, lv;
    hv.x = *(uint32_t*)&h01; hv.y = *(uint32_t*)&h23;
    lv.x = *(uint32_t*)&l01; lv.y = *(uint32_t*)&l23;
    *(uint2*)(ahi + i) = hv;
    *(uint2*)(alo + i) = lv;
}

// ---------------- split B: [K,N] fp32 -> bf16 hi/lo ----------------
__global__ __launch_bounds__(256)
void split_b_kernel(const float* __restrict__ B,
                    __nv_bfloat16* __restrict__ bhi,
                    __nv_bfloat16* __restrict__ blo)
{
    const int idx = blockIdx.x * 256 + threadIdx.x;
    if (idx >= KH * NE) return;
    const float v = B[idx];
    const __nv_bfloat16 h = __float2bfloat16(v);
    bhi[idx] = h;
    blo[idx] = __float2bfloat16(v - __bfloat162float(h));
}

// ---------------- GEMM: 3-term split-bf16 mma.sync, cp.async pipeline --------
__global__ __launch_bounds__(256)
void gate_gemm_mma(const __nv_bfloat16* __restrict__ Ahi,
                   const __nv_bfloat16* __restrict__ Alo,
                   const __nv_bfloat16* __restrict__ Bhi,
                   const __nv_bfloat16* __restrict__ Blo,
                   float* __restrict__ C)
{
    extern __shared__ char smem[];
    const uint32_t sb = smem_u32(smem);
    const int tid = threadIdx.x;
    const int wid = tid >> 5, lane = tid & 31;
    const int Mbase = blockIdx.y * BM, Nbase = blockIdx.x * BN;
    const int mw = (wid & 3) * 32;
    const int nw = (wid >> 2) * 64;

    const int l7 = lane & 7, l8 = (lane >> 3) & 1, l16 = lane >> 4;
    uint32_t a_rel[2];
    #pragma unroll
    for (int tm = 0; tm < 2; ++tm)
        a_rel[tm] = (uint32_t)((mw + 16 * tm + l7 + 8 * l8) * 80 + l16 * 16);
    uint32_t b_rel[8];
    #pragma unroll
    for (int tn = 0; tn < 8; ++tn)
        b_rel[tn] = (uint32_t)((l7 + 8 * l8) * 272 + (nw + 8 * tn) * 2);

    // cp.async coords (2 chunks per thread per split)
    const int ar0 = tid >> 2, ac4 = tid & 3;      // A: rows ar0, ar0+64
    const int bk0 = tid >> 4, bch = tid & 15;     // B: k rows bk0, bk0+16

    auto issue = [&](int c, int s) {
        const uint32_t buf = sb + (uint32_t)(s * STAGE);
        const int kb = c * 32;
        #pragma unroll
        for (int h = 0; h < 2; ++h) {
            const int r = ar0 + h * 64;
            const size_t asrc = (size_t)(Mbase + r) * KH + kb + ac4 * 8;
            cpa16(buf + AHI_OFF + r * 80 + ac4 * 16, Ahi + asrc);
            cpa16(buf + ALO_OFF + r * 80 + ac4 * 16, Alo + asrc);
            const int kk = bk0 + h * 16;
            const size_t bsrc = (size_t)(kb + kk) * NE + Nbase + bch * 8;
            cpa16(buf + BHI_OFF + kk * 272 + bch * 16, Bhi + bsrc);
            cpa16(buf + BLO_OFF + kk * 272 + bch * 16, Blo + bsrc);
        }
    };

    float acc[2][8][4];
    #pragma unroll
    for (int i = 0; i < 2; ++i)
        #pragma unroll
        for (int j = 0; j < 8; ++j)
            #pragma unroll
            for (int k = 0; k < 4; ++k) acc[i][j][k] = 0.0f;

    issue(0, 0); asm volatile("cp.async.commit_group;" ::: "memory");
    issue(1, 1); asm volatile("cp.async.commit_group;" ::: "memory");
    issue(2, 2); asm volatile("cp.async.commit_group;" ::: "memory");

    for (int c = 0; c < NCH_ST; ++c) {
        asm volatile("cp.async.wait_group 2;" ::: "memory");
        __syncthreads();
        const uint32_t stg = sb + (uint32_t)((c & 3) * STAGE);

        #pragma unroll
        for (int ks = 0; ks < 2; ++ks) {
            uint32_t ah[2][4], al[2][4];
            #pragma unroll
            for (int tm = 0; tm < 2; ++tm) {
                ldsm_x4(ah[tm], stg + AHI_OFF + a_rel[tm] + ks * 32);
                ldsm_x4(al[tm], stg + ALO_OFF + a_rel[tm] + ks * 32);
            }
            #pragma unroll
            for (int tn = 0; tn < 8; ++tn) {
                uint32_t bh[2], bl[2];
                ldsm_x2t(bh, stg + BHI_OFF + b_rel[tn] + ks * 4352);
                ldsm_x2t(bl, stg + BLO_OFF + b_rel[tn] + ks * 4352);
                #pragma unroll
                for (int tm = 0; tm < 2; ++tm) {
                    mma_bf16(acc[tm][tn], ah[tm], bh);
                    mma_bf16(acc[tm][tn], al[tm], bh);
                    mma_bf16(acc[tm][tn], ah[tm], bl);
                }
            }
        }
        if (c + 3 < NCH_ST) issue(c + 3, (c + 3) & 3);
        asm volatile("cp.async.commit_group;" ::: "memory");
    }

    #pragma unroll
    for (int tm = 0; tm < 2; ++tm) {
        const int r0 = Mbase + mw + 16 * tm + (lane >> 2);
        #pragma unroll
        for (int tn = 0; tn < 8; ++tn) {
            const int cc = Nbase + nw + 8 * tn + 2 * (lane & 3);
            float2 v0, v1;
            v0.x = acc[tm][tn][0]; v0.y = acc[tm][tn][1];
            v1.x = acc[tm][tn][2]; v1.y = acc[tm][tn][3];
            *(float2*)&C[(size_t)r0 * NE + cc] = v0;
            *(float2*)&C[(size_t)(r0 + 8) * NE + cc] = v1;
        }
    }
}

// ---------------- pass 1: route + margin detection ----------------
__global__ __launch_bounds__(256)
void route_pass1(const float* __restrict__ logits,
                 const float* __restrict__ bias,
                 float* __restrict__ out_idx,
                 float* __restrict__ out_w,
                 int* __restrict__ list,
                 int T)
{
    const int gwarp = (blockIdx.x * blockDim.x + threadIdx.x) >> 5;
    const int lane = threadIdx.x & 31;
    if (gwarp >= T) return;

    const float* lp = logits + (size_t)gwarp * NE;

    float s[8];
    #pragma unroll
    for (int j = 0; j < 8; ++j) {
        const int e = lane * 8 + j;
        s[j] = 1.0f / (1.0f + expf(-lp[e])) + bias[e];
    }

    float m1 = -1e30f, m2 = -1e30f;
    #pragma unroll
    for (int j = 0; j < 8; ++j) {
        const float v = s[j];
        if (v > m1) { m2 = m1; m1 = v; }
        else if (v > m2) { m2 = v; }
    }
    #pragma unroll
    for (int off = 1; off < 4; off <<= 1) {
        const float o1 = __shfl_xor_sync(0xffffffffu, m1, off);
        const float o2 = __shfl_xor_sync(0xffffffffu, m2, off);
        const float n1 = fmaxf(m1, o1);
        const float n2 = fmaxf(fminf(m1, o1), fmaxf(m2, o2));
        m1 = n1; m2 = n2;
    }
    const float gscore = m1 + m2;

    float gs[N_GROUP];
    #pragma unroll
    for (int g = 0; g < N_GROUP; ++g)
        gs[g] = __shfl_sync(0xffffffffu, gscore, g * 4);

    unsigned gmask = 0;
    float g4 = 0.0f, g5 = 0.0f;
    #pragma unroll
    for (int t = 0; t < 5; ++t) {
        int best = 0; float bv = -1e30f;
        #pragma unroll
        for (int g = 0; g < N_GROUP; ++g)
            if (!((gmask >> g) & 1u) && gs[g] > bv) { bv = gs[g]; best = g; }
        if (t < 4) { gmask |= 1u << best; if (t == 3) g4 = bv; }
        else g5 = bv;
    }
    bool flag = (g4 - g5) < TAU_G;

    const bool sel = (gmask >> (lane >> 2)) & 1u;
    float mv[8];
    #pragma unroll
    for (int j = 0; j < 8; ++j) mv[j] = sel ? s[j] : 0.0f;

    bool used[8];
    #pragma unroll
    for (int j = 0; j < 8; ++j) used[j] = false;

    float my_v = 0.0f; int my_i = 0; float vsum = 0.0f;
    float prev = 0.0f;
    #pragma unroll
    for (int t = 0; t < TOP_K + 1; ++t) {
        float bv = -1e30f; int bi = NE;
        #pragma unroll
        for (int j = 0; j < 8; ++j) {
            if (!used[j]) {
                const float v = mv[j];
                const int e = lane * 8 + j;
                if (v > bv || (v == bv && e < bi)) { bv = v; bi = e; }
            }
        }
        #pragma unroll
        for (int off = 16; off > 0; off >>= 1) {
            const float ov = __shfl_xor_sync(0xffffffffu, bv, off);
            const int   oi = __shfl_xor_sync(0xffffffffu, bi, off);
            if (ov > bv || (ov == bv && oi < bi)) { bv = ov; bi = oi; }
        }
        if (t > 0) flag = flag || ((prev - bv) < TAU_E);
        prev = bv;
        if (t < TOP_K) {
            if ((bi >> 3) == lane) used[bi & 7] = true;
            if (lane == t) { my_v = bv; my_i = bi; }
            vsum += bv;
        }
    }

    const float scale = ROUTED_SCALE / (vsum + 1e-20f);
    if (lane < TOP_K) {
        out_idx[(size_t)gwarp * TOP_K + lane] = (float)my_i;
        out_w  [(size_t)gwarp * TOP_K + lane] = my_v * scale;
    }
    if (flag && lane == 0) {
        const int p = atomicAdd(&g_count, 1);
        if (p < MAX_T) list[p] = gwarp;
    }
}

// ---------------- fallback: exact fp32 logits, one token per CTA ----------------
__global__ __launch_bounds__(256)
void fb_gemm(const float* __restrict__ A,
             const float* __restrict__ B,
             float* __restrict__ logits,
             const int* __restrict__ list)
{
    const int w = blockIdx.x;
    if (w >= g_count) return;
    const int token = list[w];

    __shared__ float As[KH];
    const int tid = threadIdx.x;
    {
        const float* arow = A + (size_t)token * KH;
        #pragma unroll
        for (int i = 0; i < KH / 4 / 256; ++i) {
            const int k4 = i * 256 + tid;
            *(float4*)&As[k4 * 4] = *(const float4*)(arow + k4 * 4);
        }
    }
    __syncthreads();

    const int e = tid;
    float acc = 0.0f;
    #pragma unroll 16
    for (int k = 0; k < KH; ++k)
        acc = fmaf(As[k], B[(size_t)k * NE + e], acc);

    logits[(size_t)token * NE + e] = acc;
}

// ---------------- pass 2: exact re-route of marked tokens ----------------
__global__ __launch_bounds__(256)
void route_pass2(const float* __restrict__ logits,
                 const float* __restrict__ bias,
                 float* __restrict__ out_idx,
                 float* __restrict__ out_w,
                 const int* __restrict__ list)
{
    const int w = (blockIdx.x * blockDim.x + threadIdx.x) >> 5;
    const int lane = threadIdx.x & 31;
    if (w >= g_count) return;
    const int token = list[w];

    const float* lp = logits + (size_t)token * NE;

    float s[8];
    #pragma unroll
    for (int j = 0; j < 8; ++j) {
        const int e = lane * 8 + j;
        s[j] = 1.0f / (1.0f + expf(-lp[e])) + bias[e];
    }

    float m1 = -1e30f, m2 = -1e30f;
    #pragma unroll
    for (int j = 0; j < 8; ++j) {
        const float v = s[j];
        if (v > m1) { m2 = m1; m1 = v; }
        else if (v > m2) { m2 = v; }
    }
    #pragma unroll
    for (int off = 1; off < 4; off <<= 1) {
        const float o1 = __shfl_xor_sync(0xffffffffu, m1, off);
        const float o2 = __shfl_xor_sync(0xffffffffu, m2, off);
        const float n1 = fmaxf(m1, o1);
        const float n2 = fmaxf(fminf(m1, o1), fmaxf(m2, o2));
        m1 = n1; m2 = n2;
    }
    const float gscore = m1 + m2;

    float gs[N_GROUP];
    #pragma unroll
    for (int g = 0; g < N_GROUP; ++g)
        gs[g] = __shfl_sync(0xffffffffu, gscore, g * 4);

    unsigned gmask = 0;
    #pragma unroll
    for (int t = 0; t < TOPK_GROUP; ++t) {
        int best = 0; float bv = -1e30f;
        #pragma unroll
        for (int g = 0; g < N_GROUP; ++g)
            if (!((gmask >> g) & 1u) && gs[g] > bv) { bv = gs[g]; best = g; }
        gmask |= 1u << best;
    }

    const bool sel = (gmask >> (lane >> 2)) & 1u;
    float mv[8];
    #pragma unroll
    for (int j = 0; j < 8; ++j) mv[j] = sel ? s[j] : 0.0f;

    bool used[8];
    #pragma unroll
    for (int j = 0; j < 8; ++j) used[j] = false;

    float my_v = 0.0f; int my_i = 0; float vsum = 0.0f;
    #pragma unroll
    for (int t = 0; t < TOP_K; ++t) {
        float bv = -1e30f; int bi = NE;
        #pragma unroll
        for (int j = 0; j < 8; ++j) {
            if (!used[j]) {
                const float v = mv[j];
                const int e = lane * 8 + j;
                if (v > bv || (v == bv && e < bi)) { bv = v; bi = e; }
            }
        }
        #pragma unroll
        for (int off = 16; off > 0; off >>= 1) {
            const float ov = __shfl_xor_sync(0xffffffffu, bv, off);
            const int   oi = __shfl_xor_sync(0xffffffffu, bi, off);
            if (ov > bv || (ov == bv && oi < bi)) { bv = ov; bi = oi; }
        }
        if ((bi >> 3) == lane) used[bi & 7] = true;
        if (lane == t) { my_v = bv; my_i = bi; }
        vsum += bv;
    }

    const float scale = ROUTED_SCALE / (vsum + 1e-20f);
    if (lane < TOP_K) {
        out_idx[(size_t)token * TOP_K + lane] = (float)my_i;
        out_w  [(size_t)token * TOP_K + lane] = my_v * scale;
    }
}

// ---------------- launch ----------------
extern "C" void kernel_launch(void* const* d_in, const int* in_sizes, int n_in,
                              void* d_out, int out_size)
{
    const float* hs   = (const float*)d_in[0];
    const float* wk   = (const float*)d_in[1];
    const float* bias = (const float*)d_in[2];

    const int T = in_sizes[0] / KH;   // 16384

    float* logits;      cudaGetSymbolAddress((void**)&logits, g_logits);
    __nv_bfloat16 *ahi, *alo, *bhi, *blo;
    cudaGetSymbolAddress((void**)&ahi, g_ahi);
    cudaGetSymbolAddress((void**)&alo, g_alo);
    cudaGetSymbolAddress((void**)&bhi, g_bhi);
    cudaGetSymbolAddress((void**)&blo, g_blo);
    int* list;          cudaGetSymbolAddress((void**)&list, g_list);

    float* out_f = (float*)d_out;
    float* out_idx = out_f;
    float* out_w   = out_f + (size_t)T * TOP_K;

    init_kernel<<<1, 1>>>();
    split_b_kernel<<<(KH * NE + 255) / 256, 256>>>(wk, bhi, blo);
    split_a_kernel<<<(int)(((size_t)T * KH / 4) / 256), 256>>>(hs, ahi, alo);

    cudaFuncSetAttribute(gate_gemm_mma, cudaFuncAttributeMaxDynamicSharedMemorySize, SMEM_TOTAL);
    dim3 grid(NE / BN, T / BM);
    gate_gemm_mma<<<grid, 256, SMEM_TOTAL>>>(ahi, alo, bhi, blo, logits);

    route_pass1<<<(T + 7) / 8, 256>>>(logits, bias, out_idx, out_w, list, T);
    fb_gemm<<<MAX_T, 256>>>(hs, wk, logits, list);
    route_pass2<<<(MAX_T + 7) / 8, 256>>>(logits, bias, out_idx, out_w, list);
}

// round 10
// speedup vs baseline: 4.8001x; 1.1143x over previous
#include <cuda_runtime.h>
#include <cuda_bf16.h>
#include <math.h>
#include <stdint.h>

// ---------------- Problem constants ----------------
#define NE 256
#define KH 7168
#define MAX_T 16384
#define TOPK_GROUP 4
#define TOP_K 8
#define ROUTED_SCALE 2.5f
#define N_GROUP 8

#define TAU_E 3e-5f
#define TAU_G 1e-4f

// ---------------- GEMM config ----------------
#define BM 128
#define BN 128
#define NCH_ST (KH / 32)        // 224 stages of K=32
// smem stage layout (bytes)
#define AHI_OFF 0
#define ALO_OFF 10240
#define BHI_OFF 20480
#define BLO_OFF 29184
#define STAGE   37888
#define NSTAGE  3
#define SMEM_TOTAL (NSTAGE * STAGE)   // 113664  -> 2 CTAs/SM

// ---------------- device scratch ----------------
__device__ float g_logits[MAX_T * NE];
__device__ __nv_bfloat16 g_ahi[(size_t)MAX_T * KH];
__device__ __nv_bfloat16 g_alo[(size_t)MAX_T * KH];
__device__ __nv_bfloat16 g_bhi[KH * NE];
__device__ __nv_bfloat16 g_blo[KH * NE];
__device__ int g_list[MAX_T];
__device__ int g_count;

// ---------------- helpers ----------------
__device__ __forceinline__ uint32_t smem_u32(const void* p) {
    uint32_t a;
    asm("{ .reg .u64 t; cvta.to.shared.u64 t, %1; cvt.u32.u64 %0, t; }" : "=r"(a) : "l"(p));
    return a;
}
__device__ __forceinline__ void cpa16(uint32_t dst, const void* src) {
    asm volatile("cp.async.cg.shared.global [%0], [%1], 16;" :: "r"(dst), "l"(src));
}
__device__ __forceinline__ void ldsm_x4(uint32_t* r, uint32_t addr) {
    asm volatile("ldmatrix.sync.aligned.m8n8.x4.shared.b16 {%0,%1,%2,%3}, [%4];"
                 : "=r"(r[0]), "=r"(r[1]), "=r"(r[2]), "=r"(r[3]) : "r"(addr));
}
__device__ __forceinline__ void ldsm_x2t(uint32_t* r, uint32_t addr) {
    asm volatile("ldmatrix.sync.aligned.m8n8.x2.trans.shared.b16 {%0,%1}, [%2];"
                 : "=r"(r[0]), "=r"(r[1]) : "r"(addr));
}
__device__ __forceinline__ void mma_bf16(float* c, const uint32_t* a, const uint32_t* b) {
    asm volatile("mma.sync.aligned.m16n8k16.row.col.f32.bf16.bf16.f32 "
                 "{%0,%1,%2,%3}, {%4,%5,%6,%7}, {%8,%9}, {%0,%1,%2,%3};"
                 : "+f"(c[0]), "+f"(c[1]), "+f"(c[2]), "+f"(c[3])
                 : "r"(a[0]), "r"(a[1]), "r"(a[2]), "r"(a[3]), "r"(b[0]), "r"(b[1]));
}

__global__ void init_kernel() { g_count = 0; }

// ---------------- split A: [T,KH] fp32 -> bf16 hi/lo ----------------
__global__ __launch_bounds__(256)
void split_a_kernel(const float* __restrict__ A,
                    __nv_bfloat16* __restrict__ ahi,
                    __nv_bfloat16* __restrict__ alo)
{
    const size_t i = ((size_t)blockIdx.x * 256 + threadIdx.x) * 4;
    const float4 v = *(const float4*)(A + i);
    __nv_bfloat162 h01 = __floats2bfloat162_rn(v.x, v.y);
    __nv_bfloat162 h23 = __floats2bfloat162_rn(v.z, v.w);
    __nv_bfloat162 l01 = __floats2bfloat162_rn(v.x - __bfloat162float(h01.x),
                                               v.y - __bfloat162float(h01.y));
    __nv_bfloat162 l23 = __floats2bfloat162_rn(v.z - __bfloat162float(h23.x),
                                               v.w - __bfloat162float(h23.y));
    uint2 hv, lv;
    hv.x = *(uint32_t*)&h01; hv.y = *(uint32_t*)&h23;
    lv.x = *(uint32_t*)&l01; lv.y = *(uint32_t*)&l23;
    *(uint2*)(ahi + i) = hv;
    *(uint2*)(alo + i) = lv;
}

// ---------------- split B: [K,N] fp32 -> bf16 hi/lo ----------------
__global__ __launch_bounds__(256)
void split_b_kernel(const float* __restrict__ B,
                    __nv_bfloat16* __restrict__ bhi,
                    __nv_bfloat16* __restrict__ blo)
{
    const int idx = blockIdx.x * 256 + threadIdx.x;
    if (idx >= KH * NE) return;
    const float v = B[idx];
    const __nv_bfloat16 h = __float2bfloat16(v);
    bhi[idx] = h;
    blo[idx] = __float2bfloat16(v - __bfloat162float(h));
}

// ---------------- GEMM: 3-term split-bf16 mma.sync, 3-stage cp.async, occ 2 ---
__global__ __launch_bounds__(256, 2)
void gate_gemm_mma(const __nv_bfloat16* __restrict__ Ahi,
                   const __nv_bfloat16* __restrict__ Alo,
                   const __nv_bfloat16* __restrict__ Bhi,
                   const __nv_bfloat16* __restrict__ Blo,
                   float* __restrict__ C)
{
    extern __shared__ char smem[];
    const uint32_t sb = smem_u32(smem);
    const int tid = threadIdx.x;
    const int wid = tid >> 5, lane = tid & 31;
    const int Mbase = blockIdx.y * BM, Nbase = blockIdx.x * BN;
    const int mw = (wid & 3) * 32;
    const int nw = (wid >> 2) * 64;

    const int l7 = lane & 7, l8 = (lane >> 3) & 1, l16 = lane >> 4;
    uint32_t a_rel[2];
    #pragma unroll
    for (int tm = 0; tm < 2; ++tm)
        a_rel[tm] = (uint32_t)((mw + 16 * tm + l7 + 8 * l8) * 80 + l16 * 16);
    uint32_t b_rel[8];
    #pragma unroll
    for (int tn = 0; tn < 8; ++tn)
        b_rel[tn] = (uint32_t)((l7 + 8 * l8) * 272 + (nw + 8 * tn) * 2);

    // cp.async coords (2 chunks per thread per split)
    const int ar0 = tid >> 2, ac4 = tid & 3;      // A: rows ar0, ar0+64
    const int bk0 = tid >> 4, bch = tid & 15;     // B: k rows bk0, bk0+16

    auto issue = [&](int c, int s) {
        const uint32_t buf = sb + (uint32_t)(s * STAGE);
        const int kb = c * 32;
        #pragma unroll
        for (int h = 0; h < 2; ++h) {
            const int r = ar0 + h * 64;
            const size_t asrc = (size_t)(Mbase + r) * KH + kb + ac4 * 8;
            cpa16(buf + AHI_OFF + r * 80 + ac4 * 16, Ahi + asrc);
            cpa16(buf + ALO_OFF + r * 80 + ac4 * 16, Alo + asrc);
            const int kk = bk0 + h * 16;
            const size_t bsrc = (size_t)(kb + kk) * NE + Nbase + bch * 8;
            cpa16(buf + BHI_OFF + kk * 272 + bch * 16, Bhi + bsrc);
            cpa16(buf + BLO_OFF + kk * 272 + bch * 16, Blo + bsrc);
        }
    };

    float acc[2][8][4];
    #pragma unroll
    for (int i = 0; i < 2; ++i)
        #pragma unroll
        for (int j = 0; j < 8; ++j)
            #pragma unroll
            for (int k = 0; k < 4; ++k) acc[i][j][k] = 0.0f;

    issue(0, 0); asm volatile("cp.async.commit_group;" ::: "memory");
    issue(1, 1); asm volatile("cp.async.commit_group;" ::: "memory");

    int s = 0;                   // rotating stage index = c % 3
    for (int c = 0; c < NCH_ST; ++c) {
        asm volatile("cp.async.wait_group 1;" ::: "memory");
        __syncthreads();
        const uint32_t stg = sb + (uint32_t)(s * STAGE);

        #pragma unroll
        for (int ks = 0; ks < 2; ++ks) {
            uint32_t ah[2][4], al[2][4];
            #pragma unroll
            for (int tm = 0; tm < 2; ++tm) {
                ldsm_x4(ah[tm], stg + AHI_OFF + a_rel[tm] + ks * 32);
                ldsm_x4(al[tm], stg + ALO_OFF + a_rel[tm] + ks * 32);
            }
            #pragma unroll
            for (int tn = 0; tn < 8; ++tn) {
                uint32_t bh[2], bl[2];
                ldsm_x2t(bh, stg + BHI_OFF + b_rel[tn] + ks * 4352);
                ldsm_x2t(bl, stg + BLO_OFF + b_rel[tn] + ks * 4352);
                #pragma unroll
                for (int tm = 0; tm < 2; ++tm) {
                    mma_bf16(acc[tm][tn], ah[tm], bh);
                    mma_bf16(acc[tm][tn], al[tm], bh);
                    mma_bf16(acc[tm][tn], ah[tm], bl);
                }
            }
        }
        // issue stage c+2 into buffer (c+2)%3
        if (c + 2 < NCH_ST) {
            int s2 = s + 2; if (s2 >= 3) s2 -= 3;
            issue(c + 2, s2);
        }
        asm volatile("cp.async.commit_group;" ::: "memory");
        if (++s == 3) s = 0;
    }

    #pragma unroll
    for (int tm = 0; tm < 2; ++tm) {
        const int r0 = Mbase + mw + 16 * tm + (lane >> 2);
        #pragma unroll
        for (int tn = 0; tn < 8; ++tn) {
            const int cc = Nbase + nw + 8 * tn + 2 * (lane & 3);
            float2 v0, v1;
            v0.x = acc[tm][tn][0]; v0.y = acc[tm][tn][1];
            v1.x = acc[tm][tn][2]; v1.y = acc[tm][tn][3];
            *(float2*)&C[(size_t)r0 * NE + cc] = v0;
            *(float2*)&C[(size_t)(r0 + 8) * NE + cc] = v1;
        }
    }
}

// ---------------- pass 1: route + margin detection ----------------
__global__ __launch_bounds__(256)
void route_pass1(const float* __restrict__ logits,
                 const float* __restrict__ bias,
                 float* __restrict__ out_idx,
                 float* __restrict__ out_w,
                 int* __restrict__ list,
                 int T)
{
    const int gwarp = (blockIdx.x * blockDim.x + threadIdx.x) >> 5;
    const int lane = threadIdx.x & 31;
    if (gwarp >= T) return;

    const float* lp = logits + (size_t)gwarp * NE;

    float s[8];
    #pragma unroll
    for (int j = 0; j < 8; ++j) {
        const int e = lane * 8 + j;
        s[j] = 1.0f / (1.0f + expf(-lp[e])) + bias[e];
    }

    float m1 = -1e30f, m2 = -1e30f;
    #pragma unroll
    for (int j = 0; j < 8; ++j) {
        const float v = s[j];
        if (v > m1) { m2 = m1; m1 = v; }
        else if (v > m2) { m2 = v; }
    }
    #pragma unroll
    for (int off = 1; off < 4; off <<= 1) {
        const float o1 = __shfl_xor_sync(0xffffffffu, m1, off);
        const float o2 = __shfl_xor_sync(0xffffffffu, m2, off);
        const float n1 = fmaxf(m1, o1);
        const float n2 = fmaxf(fminf(m1, o1), fmaxf(m2, o2));
        m1 = n1; m2 = n2;
    }
    const float gscore = m1 + m2;

    float gs[N_GROUP];
    #pragma unroll
    for (int g = 0; g < N_GROUP; ++g)
        gs[g] = __shfl_sync(0xffffffffu, gscore, g * 4);

    unsigned gmask = 0;
    float g4 = 0.0f, g5 = 0.0f;
    #pragma unroll
    for (int t = 0; t < 5; ++t) {
        int best = 0; float bv = -1e30f;
        #pragma unroll
        for (int g = 0; g < N_GROUP; ++g)
            if (!((gmask >> g) & 1u) && gs[g] > bv) { bv = gs[g]; best = g; }
        if (t < 4) { gmask |= 1u << best; if (t == 3) g4 = bv; }
        else g5 = bv;
    }
    bool flag = (g4 - g5) < TAU_G;

    const bool sel = (gmask >> (lane >> 2)) & 1u;
    float mv[8];
    #pragma unroll
    for (int j = 0; j < 8; ++j) mv[j] = sel ? s[j] : 0.0f;

    bool used[8];
    #pragma unroll
    for (int j = 0; j < 8; ++j) used[j] = false;

    float my_v = 0.0f; int my_i = 0; float vsum = 0.0f;
    float prev = 0.0f;
    #pragma unroll
    for (int t = 0; t < TOP_K + 1; ++t) {
        float bv = -1e30f; int bi = NE;
        #pragma unroll
        for (int j = 0; j < 8; ++j) {
            if (!used[j]) {
                const float v = mv[j];
                const int e = lane * 8 + j;
                if (v > bv || (v == bv && e < bi)) { bv = v; bi = e; }
            }
        }
        #pragma unroll
        for (int off = 16; off > 0; off >>= 1) {
            const float ov = __shfl_xor_sync(0xffffffffu, bv, off);
            const int   oi = __shfl_xor_sync(0xffffffffu, bi, off);
            if (ov > bv || (ov == bv && oi < bi)) { bv = ov; bi = oi; }
        }
        if (t > 0) flag = flag || ((prev - bv) < TAU_E);
        prev = bv;
        if (t < TOP_K) {
            if ((bi >> 3) == lane) used[bi & 7] = true;
            if (lane == t) { my_v = bv; my_i = bi; }
            vsum += bv;
        }
    }

    const float scale = ROUTED_SCALE / (vsum + 1e-20f);
    if (lane < TOP_K) {
        out_idx[(size_t)gwarp * TOP_K + lane] = (float)my_i;
        out_w  [(size_t)gwarp * TOP_K + lane] = my_v * scale;
    }
    if (flag && lane == 0) {
        const int p = atomicAdd(&g_count, 1);
        if (p < MAX_T) list[p] = gwarp;
    }
}

// ---------------- fallback: exact fp32 logits, one token per CTA ----------------
__global__ __launch_bounds__(256)
void fb_gemm(const float* __restrict__ A,
             const float* __restrict__ B,
             float* __restrict__ logits,
             const int* __restrict__ list)
{
    const int w = blockIdx.x;
    if (w >= g_count) return;
    const int token = list[w];

    __shared__ float As[KH];
    const int tid = threadIdx.x;
    {
        const float* arow = A + (size_t)token * KH;
        #pragma unroll
        for (int i = 0; i < KH / 4 / 256; ++i) {
            const int k4 = i * 256 + tid;
            *(float4*)&As[k4 * 4] = *(const float4*)(arow + k4 * 4);
        }
    }
    __syncthreads();

    const int e = tid;
    float acc = 0.0f;
    #pragma unroll 16
    for (int k = 0; k < KH; ++k)
        acc = fmaf(As[k], B[(size_t)k * NE + e], acc);

    logits[(size_t)token * NE + e] = acc;
}

// ---------------- pass 2: exact re-route of marked tokens ----------------
__global__ __launch_bounds__(256)
void route_pass2(const float* __restrict__ logits,
                 const float* __restrict__ bias,
                 float* __restrict__ out_idx,
                 float* __restrict__ out_w,
                 const int* __restrict__ list)
{
    const int w = (blockIdx.x * blockDim.x + threadIdx.x) >> 5;
    const int lane = threadIdx.x & 31;
    if (w >= g_count) return;
    const int token = list[w];

    const float* lp = logits + (size_t)token * NE;

    float s[8];
    #pragma unroll
    for (int j = 0; j < 8; ++j) {
        const int e = lane * 8 + j;
        s[j] = 1.0f / (1.0f + expf(-lp[e])) + bias[e];
    }

    float m1 = -1e30f, m2 = -1e30f;
    #pragma unroll
    for (int j = 0; j < 8; ++j) {
        const float v = s[j];
        if (v > m1) { m2 = m1; m1 = v; }
        else if (v > m2) { m2 = v; }
    }
    #pragma unroll
    for (int off = 1; off < 4; off <<= 1) {
        const float o1 = __shfl_xor_sync(0xffffffffu, m1, off);
        const float o2 = __shfl_xor_sync(0xffffffffu, m2, off);
        const float n1 = fmaxf(m1, o1);
        const float n2 = fmaxf(fminf(m1, o1), fmaxf(m2, o2));
        m1 = n1; m2 = n2;
    }
    const float gscore = m1 + m2;

    float gs[N_GROUP];
    #pragma unroll
    for (int g = 0; g < N_GROUP; ++g)
        gs[g] = __shfl_sync(0xffffffffu, gscore, g * 4);

    unsigned gmask = 0;
    #pragma unroll
    for (int t = 0; t < TOPK_GROUP; ++t) {
        int best = 0; float bv = -1e30f;
        #pragma unroll
        for (int g = 0; g < N_GROUP; ++g)
            if (!((gmask >> g) & 1u) && gs[g] > bv) { bv = gs[g]; best = g; }
        gmask |= 1u << best;
    }

    const bool sel = (gmask >> (lane >> 2)) & 1u;
    float mv[8];
    #pragma unroll
    for (int j = 0; j < 8; ++j) mv[j] = sel ? s[j] : 0.0f;

    bool used[8];
    #pragma unroll
    for (int j = 0; j < 8; ++j) used[j] = false;

    float my_v = 0.0f; int my_i = 0; float vsum = 0.0f;
    #pragma unroll
    for (int t = 0; t < TOP_K; ++t) {
        float bv = -1e30f; int bi = NE;
        #pragma unroll
        for (int j = 0; j < 8; ++j) {
            if (!used[j]) {
                const float v = mv[j];
                const int e = lane * 8 + j;
                if (v > bv || (v == bv && e < bi)) { bv = v; bi = e; }
            }
        }
        #pragma unroll
        for (int off = 16; off > 0; off >>= 1) {
            const float ov = __shfl_xor_sync(0xffffffffu, bv, off);
            const int   oi = __shfl_xor_sync(0xffffffffu, bi, off);
            if (ov > bv || (ov == bv && oi < bi)) { bv = ov; bi = oi; }
        }
        if ((bi >> 3) == lane) used[bi & 7] = true;
        if (lane == t) { my_v = bv; my_i = bi; }
        vsum += bv;
    }

    const float scale = ROUTED_SCALE / (vsum + 1e-20f);
    if (lane < TOP_K) {
        out_idx[(size_t)token * TOP_K + lane] = (float)my_i;
        out_w  [(size_t)token * TOP_K + lane] = my_v * scale;
    }
}

// ---------------- launch ----------------
extern "C" void kernel_launch(void* const* d_in, const int* in_sizes, int n_in,
                              void* d_out, int out_size)
{
    const float* hs   = (const float*)d_in[0];
    const float* wk   = (const float*)d_in[1];
    const float* bias = (const float*)d_in[2];

    const int T = in_sizes[0] / KH;   // 16384

    float* logits;      cudaGetSymbolAddress((void**)&logits, g_logits);
    __nv_bfloat16 *ahi, *alo, *bhi, *blo;
    cudaGetSymbolAddress((void**)&ahi, g_ahi);
    cudaGetSymbolAddress((void**)&alo, g_alo);
    cudaGetSymbolAddress((void**)&bhi, g_bhi);
    cudaGetSymbolAddress((void**)&blo, g_blo);
    int* list;          cudaGetSymbolAddress((void**)&list, g_list);

    float* out_f = (float*)d_out;
    float* out_idx = out_f;
    float* out_w   = out_f + (size_t)T * TOP_K;

    init_kernel<<<1, 1>>>();
    split_b_kernel<<<(KH * NE + 255) / 256, 256>>>(wk, bhi, blo);
    split_a_kernel<<<(int)(((size_t)T * KH / 4) / 256), 256>>>(hs, ahi, alo);

    cudaFuncSetAttribute(gate_gemm_mma, cudaFuncAttributeMaxDynamicSharedMemorySize, SMEM_TOTAL);
    dim3 grid(NE / BN, T / BM);
    gate_gemm_mma<<<grid, 256, SMEM_TOTAL>>>(ahi, alo, bhi, blo, logits);

    route_pass1<<<(T + 7) / 8, 256>>>(logits, bias, out_idx, out_w, list, T);
    fb_gemm<<<MAX_T, 256>>>(hs, wk, logits, list);
    route_pass2<<<(MAX_T + 7) / 8, 256>>>(logits, bias, out_idx, out_w, list);
}

// round 11
// speedup vs baseline: 5.2522x; 1.0942x over previous
#include <cuda_runtime.h>
#include <cuda_bf16.h>
#include <math.h>
#include <stdint.h>

// ---------------- Problem constants ----------------
#define NE 256
#define KH 7168
#define MAX_T 16384
#define TOPK_GROUP 4
#define TOP_K 8
#define ROUTED_SCALE 2.5f
#define N_GROUP 8

#define TAU_E 3e-5f
#define TAU_G 1e-4f

// ---------------- GEMM config ----------------
#define BM 128
#define BN 128
#define NCH_ST (KH / 32)        // 224 stages of K=32
// smem stage layout (bytes)
#define AHI_OFF 0
#define ALO_OFF 10240
#define BHI_OFF 20480
#define BLO_OFF 29184
#define STAGE   37888
#define NSTAGE  3
#define SMEM_TOTAL (NSTAGE * STAGE)   // 113664 -> 2 CTAs/SM

// ---------------- device scratch ----------------
__device__ float g_logits[MAX_T * NE];
__device__ __nv_bfloat16 g_bhi[KH * NE];
__device__ __nv_bfloat16 g_blo[KH * NE];
__device__ int g_list[MAX_T];
__device__ int g_count;

// ---------------- helpers ----------------
__device__ __forceinline__ uint32_t smem_u32(const void* p) {
    uint32_t a;
    asm("{ .reg .u64 t; cvta.to.shared.u64 t, %1; cvt.u32.u64 %0, t; }" : "=r"(a) : "l"(p));
    return a;
}
__device__ __forceinline__ void cpa16(uint32_t dst, const void* src) {
    asm volatile("cp.async.cg.shared.global [%0], [%1], 16;" :: "r"(dst), "l"(src));
}
__device__ __forceinline__ void ldsm_x4(uint32_t* r, uint32_t addr) {
    asm volatile("ldmatrix.sync.aligned.m8n8.x4.shared.b16 {%0,%1,%2,%3}, [%4];"
                 : "=r"(r[0]), "=r"(r[1]), "=r"(r[2]), "=r"(r[3]) : "r"(addr));
}
__device__ __forceinline__ void ldsm_x4t(uint32_t* r, uint32_t addr) {
    asm volatile("ldmatrix.sync.aligned.m8n8.x4.trans.shared.b16 {%0,%1,%2,%3}, [%4];"
                 : "=r"(r[0]), "=r"(r[1]), "=r"(r[2]), "=r"(r[3]) : "r"(addr));
}
__device__ __forceinline__ void mma_bf16(float* c, const uint32_t* a, const uint32_t* b) {
    asm volatile("mma.sync.aligned.m16n8k16.row.col.f32.bf16.bf16.f32 "
                 "{%0,%1,%2,%3}, {%4,%5,%6,%7}, {%8,%9}, {%0,%1,%2,%3};"
                 : "+f"(c[0]), "+f"(c[1]), "+f"(c[2]), "+f"(c[3])
                 : "r"(a[0]), "r"(a[1]), "r"(a[2]), "r"(a[3]), "r"(b[0]), "r"(b[1]));
}

__global__ void init_kernel() { g_count = 0; }

// ---------------- split B: [K,N] fp32 -> bf16 hi/lo ----------------
__global__ __launch_bounds__(256)
void split_b_kernel(const float* __restrict__ B,
                    __nv_bfloat16* __restrict__ bhi,
                    __nv_bfloat16* __restrict__ blo)
{
    const int idx = blockIdx.x * 256 + threadIdx.x;
    if (idx >= KH * NE) return;
    const float v = B[idx];
    const __nv_bfloat16 h = __float2bfloat16(v);
    bhi[idx] = h;
    blo[idx] = __float2bfloat16(v - __bfloat162float(h));
}

// ---------------- GEMM: fused A-convert, 3-term split-bf16 mma.sync ----------
__global__ __launch_bounds__(256, 2)
void gate_gemm_mma(const float* __restrict__ A,
                   const __nv_bfloat16* __restrict__ Bhi,
                   const __nv_bfloat16* __restrict__ Blo,
                   float* __restrict__ C)
{
    extern __shared__ char smem[];
    const uint32_t sb = smem_u32(smem);
    const int tid = threadIdx.x;
    const int wid = tid >> 5, lane = tid & 31;
    const int Mbase = blockIdx.y * BM, Nbase = blockIdx.x * BN;
    const int mw = (wid & 3) * 32;
    const int nw = (wid >> 2) * 64;

    const int l7 = lane & 7, l8 = (lane >> 3) & 1, l16 = lane >> 4;
    uint32_t a_rel[2];
    #pragma unroll
    for (int tm = 0; tm < 2; ++tm)
        a_rel[tm] = (uint32_t)((mw + 16 * tm + l7 + 8 * l8) * 80 + l16 * 16);
    // B x4.trans: quarter q -> {k-half = q&1, n-subtile = q>>1}
    const int q = lane >> 3;
    uint32_t b4_rel[4];
    #pragma unroll
    for (int tn2 = 0; tn2 < 4; ++tn2)
        b4_rel[tn2] = (uint32_t)((l7 + 8 * (q & 1)) * 272 +
                                 (nw + 8 * (2 * tn2 + (q >> 1))) * 2);

    // A LDG coords: thread covers rows tid>>3 (+32,+64,+96), float4-chunk tid&7
    const int ar0 = tid >> 3, ac8 = tid & 7;
    const float* Aptr = A + (size_t)(Mbase + ar0) * KH + ac8 * 4;
    const uint32_t a_sts0 = (uint32_t)(ar0 * 80 + ac8 * 8);
    // B cp.async coords
    const int bk0 = tid >> 4, bch = tid & 15;

    float4 pa[4];
    auto ldgA = [&](int c) {
        const int kb = c * 32;
        #pragma unroll
        for (int h = 0; h < 4; ++h)
            pa[h] = *(const float4*)(Aptr + (size_t)(h * 32) * KH + kb);
    };
    auto stsA = [&](int s) {
        char* buf = smem + s * STAGE;
        #pragma unroll
        for (int h = 0; h < 4; ++h) {
            const float4 v = pa[h];
            __nv_bfloat162 h01 = __floats2bfloat162_rn(v.x, v.y);
            __nv_bfloat162 h23 = __floats2bfloat162_rn(v.z, v.w);
            __nv_bfloat162 l01 = __floats2bfloat162_rn(v.x - __bfloat162float(h01.x),
                                                       v.y - __bfloat162float(h01.y));
            __nv_bfloat162 l23 = __floats2bfloat162_rn(v.z - __bfloat162float(h23.x),
                                                       v.w - __bfloat162float(h23.y));
            uint2 hv, lv;
            hv.x = *(uint32_t*)&h01; hv.y = *(uint32_t*)&h23;
            lv.x = *(uint32_t*)&l01; lv.y = *(uint32_t*)&l23;
            const uint32_t off = a_sts0 + (uint32_t)(h * 32 * 80);
            *(uint2*)(buf + AHI_OFF + off) = hv;
            *(uint2*)(buf + ALO_OFF + off) = lv;
        }
    };
    auto issueB = [&](int c, int s) {
        const uint32_t buf = sb + (uint32_t)(s * STAGE);
        const int kb = c * 32;
        #pragma unroll
        for (int h = 0; h < 2; ++h) {
            const int kk = bk0 + h * 16;
            const size_t bsrc = (size_t)(kb + kk) * NE + Nbase + bch * 8;
            cpa16(buf + BHI_OFF + kk * 272 + bch * 16, Bhi + bsrc);
            cpa16(buf + BLO_OFF + kk * 272 + bch * 16, Blo + bsrc);
        }
    };

    float acc[2][8][4];
    #pragma unroll
    for (int i = 0; i < 2; ++i)
        #pragma unroll
        for (int j = 0; j < 8; ++j)
            #pragma unroll
            for (int k = 0; k < 4; ++k) acc[i][j][k] = 0.0f;

    // prologue
    ldgA(0); stsA(0); ldgA(1);
    issueB(0, 0); asm volatile("cp.async.commit_group;" ::: "memory");
    issueB(1, 1); asm volatile("cp.async.commit_group;" ::: "memory");

    int s = 0;
    for (int c = 0; c < NCH_ST; ++c) {
        asm volatile("cp.async.wait_group 1;" ::: "memory");
        __syncthreads();
        const uint32_t stg = sb + (uint32_t)(s * STAGE);

        // feed the pipeline (A regs -> smem for c+1; LDG c+2; cp.async B c+2)
        if (c + 1 < NCH_ST) {
            int s1 = s + 1; if (s1 >= 3) s1 -= 3;
            stsA(s1);
        }
        if (c + 2 < NCH_ST) {
            ldgA(c + 2);
            int s2 = s + 2; if (s2 >= 3) s2 -= 3;
            issueB(c + 2, s2);
        }
        asm volatile("cp.async.commit_group;" ::: "memory");

        #pragma unroll
        for (int ks = 0; ks < 2; ++ks) {
            uint32_t ah[2][4], al[2][4];
            #pragma unroll
            for (int tm = 0; tm < 2; ++tm) {
                ldsm_x4(ah[tm], stg + AHI_OFF + a_rel[tm] + ks * 32);
                ldsm_x4(al[tm], stg + ALO_OFF + a_rel[tm] + ks * 32);
            }
            #pragma unroll
            for (int tn2 = 0; tn2 < 4; ++tn2) {
                uint32_t bh4[4], bl4[4];
                ldsm_x4t(bh4, stg + BHI_OFF + b4_rel[tn2] + ks * 4352);
                ldsm_x4t(bl4, stg + BLO_OFF + b4_rel[tn2] + ks * 4352);
                #pragma unroll
                for (int half = 0; half < 2; ++half) {
                    const int tn = 2 * tn2 + half;
                    #pragma unroll
                    for (int tm = 0; tm < 2; ++tm) {
                        mma_bf16(acc[tm][tn], ah[tm], bh4 + 2 * half);
                        mma_bf16(acc[tm][tn], al[tm], bh4 + 2 * half);
                        mma_bf16(acc[tm][tn], ah[tm], bl4 + 2 * half);
                    }
                }
            }
        }
        if (++s == 3) s = 0;
    }

    #pragma unroll
    for (int tm = 0; tm < 2; ++tm) {
        const int r0 = Mbase + mw + 16 * tm + (lane >> 2);
        #pragma unroll
        for (int tn = 0; tn < 8; ++tn) {
            const int cc = Nbase + nw + 8 * tn + 2 * (lane & 3);
            float2 v0, v1;
            v0.x = acc[tm][tn][0]; v0.y = acc[tm][tn][1];
            v1.x = acc[tm][tn][2]; v1.y = acc[tm][tn][3];
            *(float2*)&C[(size_t)r0 * NE + cc] = v0;
            *(float2*)&C[(size_t)(r0 + 8) * NE + cc] = v1;
        }
    }
}

// ---------------- pass 1: route + margin detection ----------------
__global__ __launch_bounds__(256)
void route_pass1(const float* __restrict__ logits,
                 const float* __restrict__ bias,
                 float* __restrict__ out_idx,
                 float* __restrict__ out_w,
                 int* __restrict__ list,
                 int T)
{
    const int gwarp = (blockIdx.x * blockDim.x + threadIdx.x) >> 5;
    const int lane = threadIdx.x & 31;
    if (gwarp >= T) return;

    const float* lp = logits + (size_t)gwarp * NE;

    float s[8];
    #pragma unroll
    for (int j = 0; j < 8; ++j) {
        const int e = lane * 8 + j;
        s[j] = 1.0f / (1.0f + expf(-lp[e])) + bias[e];
    }

    float m1 = -1e30f, m2 = -1e30f;
    #pragma unroll
    for (int j = 0; j < 8; ++j) {
        const float v = s[j];
        if (v > m1) { m2 = m1; m1 = v; }
        else if (v > m2) { m2 = v; }
    }
    #pragma unroll
    for (int off = 1; off < 4; off <<= 1) {
        const float o1 = __shfl_xor_sync(0xffffffffu, m1, off);
        const float o2 = __shfl_xor_sync(0xffffffffu, m2, off);
        const float n1 = fmaxf(m1, o1);
        const float n2 = fmaxf(fminf(m1, o1), fmaxf(m2, o2));
        m1 = n1; m2 = n2;
    }
    const float gscore = m1 + m2;

    float gs[N_GROUP];
    #pragma unroll
    for (int g = 0; g < N_GROUP; ++g)
        gs[g] = __shfl_sync(0xffffffffu, gscore, g * 4);

    unsigned gmask = 0;
    float g4 = 0.0f, g5 = 0.0f;
    #pragma unroll
    for (int t = 0; t < 5; ++t) {
        int best = 0; float bv = -1e30f;
        #pragma unroll
        for (int g = 0; g < N_GROUP; ++g)
            if (!((gmask >> g) & 1u) && gs[g] > bv) { bv = gs[g]; best = g; }
        if (t < 4) { gmask |= 1u << best; if (t == 3) g4 = bv; }
        else g5 = bv;
    }
    bool flag = (g4 - g5) < TAU_G;

    const bool sel = (gmask >> (lane >> 2)) & 1u;
    float mv[8];
    #pragma unroll
    for (int j = 0; j < 8; ++j) mv[j] = sel ? s[j] : 0.0f;

    bool used[8];
    #pragma unroll
    for (int j = 0; j < 8; ++j) used[j] = false;

    float my_v = 0.0f; int my_i = 0; float vsum = 0.0f;
    float prev = 0.0f;
    #pragma unroll
    for (int t = 0; t < TOP_K + 1; ++t) {
        float bv = -1e30f; int bi = NE;
        #pragma unroll
        for (int j = 0; j < 8; ++j) {
            if (!used[j]) {
                const float v = mv[j];
                const int e = lane * 8 + j;
                if (v > bv || (v == bv && e < bi)) { bv = v; bi = e; }
            }
        }
        #pragma unroll
        for (int off = 16; off > 0; off >>= 1) {
            const float ov = __shfl_xor_sync(0xffffffffu, bv, off);
            const int   oi = __shfl_xor_sync(0xffffffffu, bi, off);
            if (ov > bv || (ov == bv && oi < bi)) { bv = ov; bi = oi; }
        }
        if (t > 0) flag = flag || ((prev - bv) < TAU_E);
        prev = bv;
        if (t < TOP_K) {
            if ((bi >> 3) == lane) used[bi & 7] = true;
            if (lane == t) { my_v = bv; my_i = bi; }
            vsum += bv;
        }
    }

    const float scale = ROUTED_SCALE / (vsum + 1e-20f);
    if (lane < TOP_K) {
        out_idx[(size_t)gwarp * TOP_K + lane] = (float)my_i;
        out_w  [(size_t)gwarp * TOP_K + lane] = my_v * scale;
    }
    if (flag && lane == 0) {
        const int p = atomicAdd(&g_count, 1);
        if (p < MAX_T) list[p] = gwarp;
    }
}

// ------- fused fallback: exact fp32 logits + re-route, one token per CTA -------
__global__ __launch_bounds__(256)
void fb_route(const float* __restrict__ A,
              const float* __restrict__ B,
              const float* __restrict__ bias,
              float* __restrict__ out_idx,
              float* __restrict__ out_w,
              const int* __restrict__ list)
{
    const int w = blockIdx.x;
    if (w >= g_count) return;
    const int token = list[w];

    __shared__ float As[KH];
    __shared__ float sc[NE];
    const int tid = threadIdx.x;
    {
        const float* arow = A + (size_t)token * KH;
        #pragma unroll
        for (int i = 0; i < KH / 4 / 256; ++i) {
            const int k4 = i * 256 + tid;
            *(float4*)&As[k4 * 4] = *(const float4*)(arow + k4 * 4);
        }
    }
    __syncthreads();

    {   // exact logit + score for expert = tid
        float acc = 0.0f;
        #pragma unroll 16
        for (int k = 0; k < KH; ++k)
            acc = fmaf(As[k], B[(size_t)k * NE + tid], acc);
        sc[tid] = 1.0f / (1.0f + expf(-acc)) + bias[tid];
    }
    __syncthreads();

    if (tid >= 32) return;
    const int lane = tid;

    float s[8];
    #pragma unroll
    for (int j = 0; j < 8; ++j) s[j] = sc[lane * 8 + j];

    float m1 = -1e30f, m2 = -1e30f;
    #pragma unroll
    for (int j = 0; j < 8; ++j) {
        const float v = s[j];
        if (v > m1) { m2 = m1; m1 = v; }
        else if (v > m2) { m2 = v; }
    }
    #pragma unroll
    for (int off = 1; off < 4; off <<= 1) {
        const float o1 = __shfl_xor_sync(0xffffffffu, m1, off);
        const float o2 = __shfl_xor_sync(0xffffffffu, m2, off);
        const float n1 = fmaxf(m1, o1);
        const float n2 = fmaxf(fminf(m1, o1), fmaxf(m2, o2));
        m1 = n1; m2 = n2;
    }
    const float gscore = m1 + m2;

    float gs[N_GROUP];
    #pragma unroll
    for (int g = 0; g < N_GROUP; ++g)
        gs[g] = __shfl_sync(0xffffffffu, gscore, g * 4);

    unsigned gmask = 0;
    #pragma unroll
    for (int t = 0; t < TOPK_GROUP; ++t) {
        int best = 0; float bv = -1e30f;
        #pragma unroll
        for (int g = 0; g < N_GROUP; ++g)
            if (!((gmask >> g) & 1u) && gs[g] > bv) { bv = gs[g]; best = g; }
        gmask |= 1u << best;
    }

    const bool sel = (gmask >> (lane >> 2)) & 1u;
    float mv[8];
    #pragma unroll
    for (int j = 0; j < 8; ++j) mv[j] = sel ? s[j] : 0.0f;

    bool used[8];
    #pragma unroll
    for (int j = 0; j < 8; ++j) used[j] = false;

    float my_v = 0.0f; int my_i = 0; float vsum = 0.0f;
    #pragma unroll
    for (int t = 0; t < TOP_K; ++t) {
        float bv = -1e30f; int bi = NE;
        #pragma unroll
        for (int j = 0; j < 8; ++j) {
            if (!used[j]) {
                const float v = mv[j];
                const int e = lane * 8 + j;
                if (v > bv || (v == bv && e < bi)) { bv = v; bi = e; }
            }
        }
        #pragma unroll
        for (int off = 16; off > 0; off >>= 1) {
            const float ov = __shfl_xor_sync(0xffffffffu, bv, off);
            const int   oi = __shfl_xor_sync(0xffffffffu, bi, off);
            if (ov > bv || (ov == bv && oi < bi)) { bv = ov; bi = oi; }
        }
        if ((bi >> 3) == lane) used[bi & 7] = true;
        if (lane == t) { my_v = bv; my_i = bi; }
        vsum += bv;
    }

    const float scale = ROUTED_SCALE / (vsum + 1e-20f);
    if (lane < TOP_K) {
        out_idx[(size_t)token * TOP_K + lane] = (float)my_i;
        out_w  [(size_t)token * TOP_K + lane] = my_v * scale;
    }
}

// ---------------- launch ----------------
extern "C" void kernel_launch(void* const* d_in, const int* in_sizes, int n_in,
                              void* d_out, int out_size)
{
    const float* hs   = (const float*)d_in[0];
    const float* wk   = (const float*)d_in[1];
    const float* bias = (const float*)d_in[2];

    const int T = in_sizes[0] / KH;   // 16384

    float* logits;      cudaGetSymbolAddress((void**)&logits, g_logits);
    __nv_bfloat16 *bhi, *blo;
    cudaGetSymbolAddress((void**)&bhi, g_bhi);
    cudaGetSymbolAddress((void**)&blo, g_blo);
    int* list;          cudaGetSymbolAddress((void**)&list, g_list);

    float* out_f = (float*)d_out;
    float* out_idx = out_f;
    float* out_w   = out_f + (size_t)T * TOP_K;

    init_kernel<<<1, 1>>>();
    split_b_kernel<<<(KH * NE + 255) / 256, 256>>>(wk, bhi, blo);

    cudaFuncSetAttribute(gate_gemm_mma, cudaFuncAttributeMaxDynamicSharedMemorySize, SMEM_TOTAL);
    dim3 grid(NE / BN, T / BM);
    gate_gemm_mma<<<grid, 256, SMEM_TOTAL>>>(hs, bhi, blo, logits);

    route_pass1<<<(T + 7) / 8, 256>>>(logits, bias, out_idx, out_w, list, T);
    fb_route<<<MAX_T, 256>>>(hs, wk, bias, out_idx, out_w, list);
}